// round 5
// baseline (speedup 1.0000x reference)
#include <cuda_runtime.h>
#include <math.h>
#include <stdint.h>

// ---------------- problem constants ----------------
#define NN 50000
#define DHID 128
#define DOUT 64
#define NGRAPH 16
#define BN_EPS 1e-5f

// ---------------- device scratch ----------------
__device__ __align__(16) float g_dinv[NN];
__device__ __align__(16) float g_bufA[NN * DHID];
__device__ __align__(16) float g_bufB[NN * DHID];
__device__ __align__(16) float g_bnsum[DHID];
__device__ __align__(16) float g_bnsq[DHID];
__device__ __align__(16) float g_pool[NGRAPH * DOUT];
__device__ __align__(16) float g_pcnt[NGRAPH];

// ---------------- init / degree / rsqrt ----------------
__global__ void k_init(int n) {
    int i = blockIdx.x * blockDim.x + threadIdx.x;
    if (i < n) g_dinv[i] = 1.0f;
    if (i < NGRAPH * DOUT) g_pool[i] = 0.0f;
    if (i < NGRAPH) g_pcnt[i] = 0.0f;
}

__global__ void k_deg(const int* __restrict__ dst, int e, int n) {
    int i = blockIdx.x * blockDim.x + threadIdx.x;
    if (i < e) {
        int d = dst[i];
        if ((unsigned)d < (unsigned)n) atomicAdd(&g_dinv[d], 1.0f);
    }
}

__global__ void k_dinv(int n) {
    int i = blockIdx.x * blockDim.x + threadIdx.x;
    if (i < n) g_dinv[i] = rsqrtf(g_dinv[i]);
}

// ---------------- tiled GEMM, FFMA2, no packing MOVs ----------------
// OUT_raw = T(X) @ W ; OUT_scaled = OUT_raw * dinv[row]^2
// T = identity or BN-affine+ReLU (scale/shift in g_bnsum/g_bnsq).
// 256 threads = 16(tx) x 16(ty). Block tile 64 x NOUT. Thread tile 4 x TN.
// X stored in smem pre-duplicated (float2{v,v}); W column-pairs packed via
// LDS.128 reinterpret. Accumulators pack column pairs (f32x2).
template <int KDIM, int NOUT, bool BNRELU>
__global__ void __launch_bounds__(256, 3)
k_gemm_t(const float* X, const float* __restrict__ W,
         float* __restrict__ OUT_raw, float* OUT_scaled, int nrows) {
    constexpr int BM = 64, BK = 16;
    constexpr int TN = NOUT / 16;        // 8 or 4
    constexpr int CP = TN / 2;           // packed col-pairs (4 or 2)
    __shared__ float2 Xs2[BK][BM];       // duplicated X values
    __shared__ float  Ws[BK][NOUT];

    const int tid = threadIdx.x;
    const int tx = tid & 15, ty = tid >> 4;
    const int row0 = blockIdx.x * BM;

    unsigned long long acc2[4][CP];
#pragma unroll
    for (int r = 0; r < 4; r++)
#pragma unroll
        for (int c = 0; c < CP; c++) acc2[r][c] = 0ull;

    const int xr = tid >> 2;             // 0..63  (X row within tile)
    const int kq = (tid & 3) * 4;        // 0,4,8,12

    for (int kb = 0; kb < KDIM; kb += BK) {
        // ---- X tile: load, optional BN+ReLU, store duplicated ----
        {
            float4 v = make_float4(0.f, 0.f, 0.f, 0.f);
            int row = row0 + xr;
            if (row < nrows)
                v = *reinterpret_cast<const float4*>(&X[(size_t)row * KDIM + kb + kq]);
            if (BNRELU) {
                v.x = fmaxf(fmaf(v.x, g_bnsum[kb + kq + 0], g_bnsq[kb + kq + 0]), 0.f);
                v.y = fmaxf(fmaf(v.y, g_bnsum[kb + kq + 1], g_bnsq[kb + kq + 1]), 0.f);
                v.z = fmaxf(fmaf(v.z, g_bnsum[kb + kq + 2], g_bnsq[kb + kq + 2]), 0.f);
                v.w = fmaxf(fmaf(v.w, g_bnsum[kb + kq + 3], g_bnsq[kb + kq + 3]), 0.f);
            }
            Xs2[kq + 0][xr] = make_float2(v.x, v.x);
            Xs2[kq + 1][xr] = make_float2(v.y, v.y);
            Xs2[kq + 2][xr] = make_float2(v.z, v.z);
            Xs2[kq + 3][xr] = make_float2(v.w, v.w);
        }
        // ---- W tile ----
        constexpr int F4 = (BK * NOUT / 4) / 256;   // float4 loads per thread
#pragma unroll
        for (int i = 0; i < F4; i++) {
            int f = tid + i * 256;
            int k = f / (NOUT / 4);
            int c = (f % (NOUT / 4)) * 4;
            *reinterpret_cast<float4*>(&Ws[k][c]) =
                *reinterpret_cast<const float4*>(&W[(size_t)(kb + k) * NOUT + c]);
        }
        __syncthreads();

        // ---- compute ----
#pragma unroll
        for (int k = 0; k < BK; k++) {
            unsigned long long xv2[4];
            {
                const ulonglong2* p =
                    reinterpret_cast<const ulonglong2*>(&Xs2[k][ty * 4]);
                ulonglong2 a = p[0], b = p[1];
                xv2[0] = a.x; xv2[1] = a.y; xv2[2] = b.x; xv2[3] = b.y;
            }
            unsigned long long wv2[CP];
            {
                const ulonglong2* p =
                    reinterpret_cast<const ulonglong2*>(&Ws[k][tx * TN]);
                ulonglong2 a = p[0];
                wv2[0] = a.x; wv2[1] = a.y;
                if (CP == 4) {
                    ulonglong2 b = p[1];
                    wv2[2] = b.x; wv2[3] = b.y;
                }
            }
#pragma unroll
            for (int r = 0; r < 4; r++)
#pragma unroll
                for (int c = 0; c < CP; c++) {
                    asm("fma.rn.f32x2 %0, %1, %2, %0;"
                        : "+l"(acc2[r][c]) : "l"(xv2[r]), "l"(wv2[c]));
                }
        }
        __syncthreads();
    }

    // ---- epilogue: raw + dinv^2-scaled ----
#pragma unroll
    for (int r = 0; r < 4; r++) {
        int row = row0 + ty * 4 + r;
        if (row >= nrows) break;
        float di = g_dinv[row];
        di *= di;
#pragma unroll
        for (int c0 = 0; c0 < CP; c0 += 2) {
            float2 p0 = *reinterpret_cast<float2*>(&acc2[r][c0]);
            float2 p1 = *reinterpret_cast<float2*>(&acc2[r][c0 + 1]);
            float4 raw = make_float4(p0.x, p0.y, p1.x, p1.y);
            size_t off = (size_t)row * NOUT + tx * TN + c0 * 2;
            *reinterpret_cast<float4*>(&OUT_raw[off]) = raw;
            float4 s4 = make_float4(raw.x * di, raw.y * di, raw.z * di, raw.w * di);
            *reinterpret_cast<float4*>(&OUT_scaled[off]) = s4;
        }
    }
}

// ---------------- edge scatter: out[d] += h[s] * dinv[s]*dinv[d] ------------
template <int NOUT>
__global__ void k_scatter(const int* __restrict__ src, const int* __restrict__ dst,
                          const float* __restrict__ h, float* __restrict__ out,
                          int e_total, int n) {
    constexpr int LPE = NOUT / 4;
    constexpr int EPW = 32 / LPE;
    int warp = (blockIdx.x * blockDim.x + threadIdx.x) >> 5;
    int lane = threadIdx.x & 31;
    int e = warp * EPW + lane / LPE;
    if (e >= e_total) return;
    int s = src[e];
    int d = dst[e];
    if ((unsigned)s >= (unsigned)n || (unsigned)d >= (unsigned)n) return;
    float w = g_dinv[s] * g_dinv[d];
    int c = (lane % LPE) * 4;
    float4 v = *reinterpret_cast<const float4*>(&h[(size_t)s * NOUT + c]);
    unsigned long long gp =
        (unsigned long long)__cvta_generic_to_global(&out[(size_t)d * NOUT + c]);
    asm volatile("red.global.add.v4.f32 [%0], {%1,%2,%3,%4};"
                 :: "l"(gp), "f"(v.x * w), "f"(v.y * w), "f"(v.z * w), "f"(v.w * w)
                 : "memory");
}

// ---------------- BN ----------------
__global__ void k_bnzero() {
    g_bnsum[threadIdx.x] = 0.0f;
    g_bnsq[threadIdx.x] = 0.0f;
}

// 256 threads: (tid&31) -> 4-col group, (tid>>5) -> row partition.
// Block-local smem reduction, then one global atomic per column per block.
__global__ void k_bnstats(const float* __restrict__ a, int n) {
    __shared__ float ssum[DHID], ssq[DHID];
    int tid = threadIdx.x;
    if (tid < DHID) { ssum[tid] = 0.0f; ssq[tid] = 0.0f; }
    __syncthreads();

    int c = (tid & 31) * 4;
    int rp = tid >> 5;                       // 0..7
    float s0 = 0, s1 = 0, s2 = 0, s3 = 0;
    float q0 = 0, q1 = 0, q2 = 0, q3 = 0;
    int stride = gridDim.x * 8;
    for (int r = blockIdx.x * 8 + rp; r < n; r += stride) {
        float4 v = *reinterpret_cast<const float4*>(&a[(size_t)r * DHID + c]);
        s0 += v.x; q0 += v.x * v.x;
        s1 += v.y; q1 += v.y * v.y;
        s2 += v.z; q2 += v.z * v.z;
        s3 += v.w; q3 += v.w * v.w;
    }
    atomicAdd(&ssum[c + 0], s0); atomicAdd(&ssq[c + 0], q0);
    atomicAdd(&ssum[c + 1], s1); atomicAdd(&ssq[c + 1], q1);
    atomicAdd(&ssum[c + 2], s2); atomicAdd(&ssq[c + 2], q2);
    atomicAdd(&ssum[c + 3], s3); atomicAdd(&ssq[c + 3], q3);
    __syncthreads();
    if (tid < DHID) {
        atomicAdd(&g_bnsum[tid], ssum[tid]);
        atomicAdd(&g_bnsq[tid], ssq[tid]);
    }
}

__global__ void k_bnfinal(const float* __restrict__ gam, const float* __restrict__ bet, float n) {
    int c = threadIdx.x;  // 128
    float mu = g_bnsum[c] / n;
    float var = g_bnsq[c] / n - mu * mu;
    float sc = rsqrtf(var + BN_EPS) * gam[c];
    g_bnsum[c] = sc;
    g_bnsq[c] = bet[c] - mu * sc;
}

// ---------------- pool: batch sorted -> run-length accumulate ----------------
#define POOL_CHUNK 128
__global__ void k_pool(const float* __restrict__ h, const int* __restrict__ batch, int n) {
    int col = threadIdx.x;  // 64
    int r0 = blockIdx.x * POOL_CHUNK;
    if (r0 >= n) return;
    int r1 = min(r0 + POOL_CHUNK, n);
    int cur = batch[r0] & (NGRAPH - 1);
    float acc = 0.0f, cacc = 0.0f;
    for (int r = r0; r < r1; r++) {
        int g = batch[r] & (NGRAPH - 1);
        if (g != cur) {
            atomicAdd(&g_pool[cur * DOUT + col], acc);
            if (col == 0) atomicAdd(&g_pcnt[cur], cacc);
            acc = 0.0f; cacc = 0.0f; cur = g;
        }
        acc += h[(size_t)r * DOUT + col];
        cacc += 1.0f;
    }
    atomicAdd(&g_pool[cur * DOUT + col], acc);
    if (col == 0) atomicAdd(&g_pcnt[cur], cacc);
}

__global__ void k_final(float* __restrict__ out, const float* __restrict__ b3) {
    int t = threadIdx.x;  // 1024
    int g = t / DOUT;
    int c = t % DOUT;
    float cnt = g_pcnt[g];
    out[t] = (cnt > 0.0f) ? (g_pool[t] / cnt + b3[c]) : 0.0f;
}

// ============================================================================
extern "C" void kernel_launch(void* const* d_in, const int* in_sizes, int n_in,
                              void* d_out, int out_size) {
    const float* x     = (const float*)d_in[0];
    const int*   ei    = (const int*)d_in[1];   // int64 coerced to int32
    const int*   batch = (const int*)d_in[2];
    const float* W1    = (const float*)d_in[3];
    const float* W2    = (const float*)d_in[5];
    const float* W3    = (const float*)d_in[7];
    const float* b3    = (const float*)d_in[8];
    const float* g1    = (const float*)d_in[9];
    const float* be1   = (const float*)d_in[10];
    const float* g2    = (const float*)d_in[11];
    const float* be2   = (const float*)d_in[12];
    float* out = (float*)d_out;

    const int n = in_sizes[2];       // 50000
    const int E = in_sizes[1] / 2;   // 800000
    const int* src = ei;
    const int* dst = ei + E;

    float* bufA; float* bufB;
    cudaGetSymbolAddress((void**)&bufA, g_bufA);
    cudaGetSymbolAddress((void**)&bufB, g_bufB);
    float* raw3 = bufA;
    float* agg3 = bufA + (size_t)NN * DOUT;

    const int TB = 256;
    int nb_n    = (n + TB - 1) / TB;
    int nb_e    = (E + TB - 1) / TB;
    int nb_gemm = (n + 63) / 64;
    int nb_sc128 = (int)(((long long)E * 32 + TB - 1) / TB);
    int nb_sc64  = (int)((((long long)(E + 1) / 2) * 32 + TB - 1) / TB);
    int nb_stats = 128;
    int nb_pool  = (n + POOL_CHUNK - 1) / POOL_CHUNK;

    // degree / norm
    k_init<<<nb_n, TB>>>(n);
    k_deg<<<nb_e, TB>>>(dst, E, n);
    k_dinv<<<nb_n, TB>>>(n);

    // ---- layer 1 ----
    k_gemm_t<256, 128, false><<<nb_gemm, 256>>>(x, W1, bufA, bufB, n);
    k_scatter<128><<<nb_sc128, TB>>>(src, dst, bufA, bufB, E, n);
    k_bnzero<<<1, DHID>>>();
    k_bnstats<<<nb_stats, 256>>>(bufB, n);
    k_bnfinal<<<1, DHID>>>(g1, be1, (float)n);

    // ---- layer 2 (BN1+ReLU fused into X load; scaled written in-place) ----
    k_gemm_t<128, 128, true><<<nb_gemm, 256>>>(bufB, W2, bufA, bufB, n);
    k_scatter<128><<<nb_sc128, TB>>>(src, dst, bufA, bufB, E, n);
    k_bnzero<<<1, DHID>>>();
    k_bnstats<<<nb_stats, 256>>>(bufB, n);
    k_bnfinal<<<1, DHID>>>(g2, be2, (float)n);

    // ---- layer 3 (BN2+ReLU fused) ----
    k_gemm_t<128, 64, true><<<nb_gemm, 256>>>(bufB, W3, raw3, agg3, n);
    k_scatter<64><<<nb_sc64, TB>>>(src, dst, raw3, agg3, E, n);

    // ---- mean pool + bias ----
    k_pool<<<nb_pool, DOUT>>>(agg3, batch, n);
    k_final<<<1, NGRAPH * DOUT>>>(out, b3);
}

// round 6
// speedup vs baseline: 1.2959x; 1.2959x over previous
#include <cuda_runtime.h>
#include <math.h>
#include <stdint.h>

// ---------------- problem constants ----------------
#define NN 50000
#define DHID 128
#define DOUT 64
#define NGRAPH 16
#define BN_EPS 1e-5f

// ---------------- device scratch ----------------
__device__ __align__(16) float g_dinv[NN];
__device__ __align__(16) float g_bufA[NN * DHID];
__device__ __align__(16) float g_bufB[NN * DHID];
__device__ __align__(16) float g_bnsum[DHID];
__device__ __align__(16) float g_bnsq[DHID];
__device__ __align__(16) float g_pool[NGRAPH * DOUT];
__device__ __align__(16) float g_pcnt[NGRAPH];

// ---------------- init / degree / rsqrt ----------------
__global__ void k_init(int n) {
    int i = blockIdx.x * blockDim.x + threadIdx.x;
    if (i < n) g_dinv[i] = 1.0f;
    if (i < NGRAPH * DOUT) g_pool[i] = 0.0f;
    if (i < NGRAPH) g_pcnt[i] = 0.0f;
}

__global__ void k_deg(const int* __restrict__ dst, int e, int n) {
    int i = blockIdx.x * blockDim.x + threadIdx.x;
    if (i < e) {
        int d = dst[i];
        if ((unsigned)d < (unsigned)n) atomicAdd(&g_dinv[d], 1.0f);
    }
}

__global__ void k_dinv(int n) {
    int i = blockIdx.x * blockDim.x + threadIdx.x;
    if (i < n) g_dinv[i] = rsqrtf(g_dinv[i]);
}

// ---------------- tf32 helpers ----------------
__device__ __forceinline__ float tf32_rna(float x) {
    unsigned u;
    asm("cvt.rna.tf32.f32 %0, %1;" : "=r"(u) : "f"(x));
    return __uint_as_float(u);
}

#define MMA_TF32(d, a, b0, b1)                                              \
    asm volatile(                                                           \
        "mma.sync.aligned.m16n8k8.row.col.f32.tf32.tf32.f32 "               \
        "{%0,%1,%2,%3}, {%4,%5,%6,%7}, {%8,%9}, {%0,%1,%2,%3};"             \
        : "+f"((d)[0]), "+f"((d)[1]), "+f"((d)[2]), "+f"((d)[3])            \
        : "r"((a)[0]), "r"((a)[1]), "r"((a)[2]), "r"((a)[3]),               \
          "r"(b0), "r"(b1))

// ---------------- tensor-core GEMM (3xTF32) + fused BN/ReLU + selfinit -----
// OUT_raw = T(X) @ W ; OUT_scaled = OUT_raw * dinv[row]^2
// 256 threads = 8 warps; block tile 128 x NOUT; warp grid 4(m) x 2(n);
// warp tile 32 x NOUT/2; mma m16n8k8 tf32 with hi/lo split (3 passes).
template <int KDIM, int NOUT, bool BNRELU>
__global__ void __launch_bounds__(256, 2)
k_gemm_mma(const float* X, const float* __restrict__ W,
           float* __restrict__ OUT_raw, float* OUT_scaled, int nrows) {
    constexpr int BM = 128, BK = 16;
    constexpr int XS = BK + 4;            // stride 20: (20m+k) distinct mod 32
    constexpr int WS = NOUT + 8;          // stride: (8k+n) distinct mod 32
    constexpr int hN = NOUT / 2;          // warp n-extent (64 or 32)
    constexpr int NT = hN / 8;            // n-tiles per warp (8 or 4)
    constexpr int MT = 2;                 // m-tiles per warp (2 x 16 = 32)

    __shared__ float Xh[BM][XS], Xl[BM][XS];
    __shared__ float Wh[BK][WS], Wl[BK][WS];

    const int tid = threadIdx.x;
    const int lane = tid & 31;
    const int wid = tid >> 5;
    const int wm = wid & 3;               // warp m index (0..3)
    const int wn = wid >> 2;              // warp n index (0..1)
    const int row0 = blockIdx.x * BM;

    float acc[MT][NT][4];
#pragma unroll
    for (int mt = 0; mt < MT; mt++)
#pragma unroll
        for (int nt = 0; nt < NT; nt++)
#pragma unroll
            for (int j = 0; j < 4; j++) acc[mt][nt][j] = 0.0f;

    for (int kb = 0; kb < KDIM; kb += BK) {
        // ---- X tile: load, optional BN+ReLU, split hi/lo ----
#pragma unroll
        for (int i = 0; i < 2; i++) {
            int rl = (tid >> 2) + i * 64;          // 0..127
            int kq = (tid & 3) * 4;
            int row = row0 + rl;
            float4 v = make_float4(0.f, 0.f, 0.f, 0.f);
            if (row < nrows)
                v = *reinterpret_cast<const float4*>(&X[(size_t)row * KDIM + kb + kq]);
            if (BNRELU) {
                v.x = fmaxf(fmaf(v.x, g_bnsum[kb + kq + 0], g_bnsq[kb + kq + 0]), 0.f);
                v.y = fmaxf(fmaf(v.y, g_bnsum[kb + kq + 1], g_bnsq[kb + kq + 1]), 0.f);
                v.z = fmaxf(fmaf(v.z, g_bnsum[kb + kq + 2], g_bnsq[kb + kq + 2]), 0.f);
                v.w = fmaxf(fmaf(v.w, g_bnsum[kb + kq + 3], g_bnsq[kb + kq + 3]), 0.f);
            }
            float4 hv, lv;
            hv.x = tf32_rna(v.x); lv.x = tf32_rna(v.x - hv.x);
            hv.y = tf32_rna(v.y); lv.y = tf32_rna(v.y - hv.y);
            hv.z = tf32_rna(v.z); lv.z = tf32_rna(v.z - hv.z);
            hv.w = tf32_rna(v.w); lv.w = tf32_rna(v.w - hv.w);
            *reinterpret_cast<float4*>(&Xh[rl][kq]) = hv;
            *reinterpret_cast<float4*>(&Xl[rl][kq]) = lv;
        }
        // ---- W tile: load, split hi/lo ----
        constexpr int F4 = (BK * NOUT / 4) / 256;   // 2 (NOUT=128) or 1 (64)
#pragma unroll
        for (int i = 0; i < F4; i++) {
            int f = tid + i * 256;
            int k = f / (NOUT / 4);
            int c = (f % (NOUT / 4)) * 4;
            float4 v = *reinterpret_cast<const float4*>(&W[(size_t)(kb + k) * NOUT + c]);
            float4 hv, lv;
            hv.x = tf32_rna(v.x); lv.x = tf32_rna(v.x - hv.x);
            hv.y = tf32_rna(v.y); lv.y = tf32_rna(v.y - hv.y);
            hv.z = tf32_rna(v.z); lv.z = tf32_rna(v.z - hv.z);
            hv.w = tf32_rna(v.w); lv.w = tf32_rna(v.w - hv.w);
            *reinterpret_cast<float4*>(&Wh[k][c]) = hv;
            *reinterpret_cast<float4*>(&Wl[k][c]) = lv;
        }
        __syncthreads();

        // ---- compute: two k8 steps ----
#pragma unroll
        for (int k8 = 0; k8 < BK; k8 += 8) {
            unsigned ah[MT][4], al[MT][4];
#pragma unroll
            for (int mt = 0; mt < MT; mt++) {
                int ar = wm * 32 + mt * 16 + (lane >> 2);
                int ac = k8 + (lane & 3);
                ah[mt][0] = __float_as_uint(Xh[ar][ac]);
                ah[mt][1] = __float_as_uint(Xh[ar + 8][ac]);
                ah[mt][2] = __float_as_uint(Xh[ar][ac + 4]);
                ah[mt][3] = __float_as_uint(Xh[ar + 8][ac + 4]);
                al[mt][0] = __float_as_uint(Xl[ar][ac]);
                al[mt][1] = __float_as_uint(Xl[ar + 8][ac]);
                al[mt][2] = __float_as_uint(Xl[ar][ac + 4]);
                al[mt][3] = __float_as_uint(Xl[ar + 8][ac + 4]);
            }
#pragma unroll
            for (int nt = 0; nt < NT; nt++) {
                int bc = wn * hN + nt * 8 + (lane >> 2);
                int bk = k8 + (lane & 3);
                unsigned bh0 = __float_as_uint(Wh[bk][bc]);
                unsigned bh1 = __float_as_uint(Wh[bk + 4][bc]);
                unsigned bl0 = __float_as_uint(Wl[bk][bc]);
                unsigned bl1 = __float_as_uint(Wl[bk + 4][bc]);
#pragma unroll
                for (int mt = 0; mt < MT; mt++) {
                    MMA_TF32(acc[mt][nt], ah[mt], bh0, bh1);
                    MMA_TF32(acc[mt][nt], ah[mt], bl0, bl1);
                    MMA_TF32(acc[mt][nt], al[mt], bh0, bh1);
                }
            }
        }
        __syncthreads();
    }

    // ---- epilogue: raw + dinv^2-scaled ----
#pragma unroll
    for (int mt = 0; mt < MT; mt++) {
        int r0 = row0 + wm * 32 + mt * 16 + (lane >> 2);
        int r1 = r0 + 8;
        float d0 = 0.f, d1 = 0.f;
        if (r0 < nrows) { d0 = g_dinv[r0]; d0 *= d0; }
        if (r1 < nrows) { d1 = g_dinv[r1]; d1 *= d1; }
#pragma unroll
        for (int nt = 0; nt < NT; nt++) {
            int col = wn * hN + nt * 8 + (lane & 3) * 2;
            if (r0 < nrows) {
                float2 raw = make_float2(acc[mt][nt][0], acc[mt][nt][1]);
                size_t off = (size_t)r0 * NOUT + col;
                *reinterpret_cast<float2*>(&OUT_raw[off]) = raw;
                *reinterpret_cast<float2*>(&OUT_scaled[off]) =
                    make_float2(raw.x * d0, raw.y * d0);
            }
            if (r1 < nrows) {
                float2 raw = make_float2(acc[mt][nt][2], acc[mt][nt][3]);
                size_t off = (size_t)r1 * NOUT + col;
                *reinterpret_cast<float2*>(&OUT_raw[off]) = raw;
                *reinterpret_cast<float2*>(&OUT_scaled[off]) =
                    make_float2(raw.x * d1, raw.y * d1);
            }
        }
    }
}

// ---------------- edge scatter: out[d] += h[s] * dinv[s]*dinv[d] ------------
template <int NOUT>
__global__ void k_scatter(const int* __restrict__ src, const int* __restrict__ dst,
                          const float* __restrict__ h, float* __restrict__ out,
                          int e_total, int n) {
    constexpr int LPE = NOUT / 4;
    constexpr int EPW = 32 / LPE;
    int warp = (blockIdx.x * blockDim.x + threadIdx.x) >> 5;
    int lane = threadIdx.x & 31;
    int e = warp * EPW + lane / LPE;
    if (e >= e_total) return;
    int s = src[e];
    int d = dst[e];
    if ((unsigned)s >= (unsigned)n || (unsigned)d >= (unsigned)n) return;
    float w = g_dinv[s] * g_dinv[d];
    int c = (lane % LPE) * 4;
    float4 v = *reinterpret_cast<const float4*>(&h[(size_t)s * NOUT + c]);
    unsigned long long gp =
        (unsigned long long)__cvta_generic_to_global(&out[(size_t)d * NOUT + c]);
    asm volatile("red.global.add.v4.f32 [%0], {%1,%2,%3,%4};"
                 :: "l"(gp), "f"(v.x * w), "f"(v.y * w), "f"(v.z * w), "f"(v.w * w)
                 : "memory");
}

// ---------------- BN ----------------
__global__ void k_bnzero() {
    g_bnsum[threadIdx.x] = 0.0f;
    g_bnsq[threadIdx.x] = 0.0f;
}

__global__ void k_bnstats(const float* __restrict__ a, int n) {
    __shared__ float ssum[DHID], ssq[DHID];
    int tid = threadIdx.x;
    if (tid < DHID) { ssum[tid] = 0.0f; ssq[tid] = 0.0f; }
    __syncthreads();

    int c = (tid & 31) * 4;
    int rp = tid >> 5;
    float s0 = 0, s1 = 0, s2 = 0, s3 = 0;
    float q0 = 0, q1 = 0, q2 = 0, q3 = 0;
    int stride = gridDim.x * 8;
    for (int r = blockIdx.x * 8 + rp; r < n; r += stride) {
        float4 v = *reinterpret_cast<const float4*>(&a[(size_t)r * DHID + c]);
        s0 += v.x; q0 += v.x * v.x;
        s1 += v.y; q1 += v.y * v.y;
        s2 += v.z; q2 += v.z * v.z;
        s3 += v.w; q3 += v.w * v.w;
    }
    atomicAdd(&ssum[c + 0], s0); atomicAdd(&ssq[c + 0], q0);
    atomicAdd(&ssum[c + 1], s1); atomicAdd(&ssq[c + 1], q1);
    atomicAdd(&ssum[c + 2], s2); atomicAdd(&ssq[c + 2], q2);
    atomicAdd(&ssum[c + 3], s3); atomicAdd(&ssq[c + 3], q3);
    __syncthreads();
    if (tid < DHID) {
        atomicAdd(&g_bnsum[tid], ssum[tid]);
        atomicAdd(&g_bnsq[tid], ssq[tid]);
    }
}

__global__ void k_bnfinal(const float* __restrict__ gam, const float* __restrict__ bet, float n) {
    int c = threadIdx.x;  // 128
    float mu = g_bnsum[c] / n;
    float var = g_bnsq[c] / n - mu * mu;
    float sc = rsqrtf(var + BN_EPS) * gam[c];
    g_bnsum[c] = sc;
    g_bnsq[c] = bet[c] - mu * sc;
}

// ---------------- pool: batch sorted -> run-length accumulate ----------------
#define POOL_CHUNK 128
__global__ void k_pool(const float* __restrict__ h, const int* __restrict__ batch, int n) {
    int col = threadIdx.x;  // 64
    int r0 = blockIdx.x * POOL_CHUNK;
    if (r0 >= n) return;
    int r1 = min(r0 + POOL_CHUNK, n);
    int cur = batch[r0] & (NGRAPH - 1);
    float acc = 0.0f, cacc = 0.0f;
    for (int r = r0; r < r1; r++) {
        int g = batch[r] & (NGRAPH - 1);
        if (g != cur) {
            atomicAdd(&g_pool[cur * DOUT + col], acc);
            if (col == 0) atomicAdd(&g_pcnt[cur], cacc);
            acc = 0.0f; cacc = 0.0f; cur = g;
        }
        acc += h[(size_t)r * DOUT + col];
        cacc += 1.0f;
    }
    atomicAdd(&g_pool[cur * DOUT + col], acc);
    if (col == 0) atomicAdd(&g_pcnt[cur], cacc);
}

__global__ void k_final(float* __restrict__ out, const float* __restrict__ b3) {
    int t = threadIdx.x;  // 1024
    int g = t / DOUT;
    int c = t % DOUT;
    float cnt = g_pcnt[g];
    out[t] = (cnt > 0.0f) ? (g_pool[t] / cnt + b3[c]) : 0.0f;
}

// ============================================================================
extern "C" void kernel_launch(void* const* d_in, const int* in_sizes, int n_in,
                              void* d_out, int out_size) {
    const float* x     = (const float*)d_in[0];
    const int*   ei    = (const int*)d_in[1];   // int64 coerced to int32
    const int*   batch = (const int*)d_in[2];
    const float* W1    = (const float*)d_in[3];
    const float* W2    = (const float*)d_in[5];
    const float* W3    = (const float*)d_in[7];
    const float* b3    = (const float*)d_in[8];
    const float* g1    = (const float*)d_in[9];
    const float* be1   = (const float*)d_in[10];
    const float* g2    = (const float*)d_in[11];
    const float* be2   = (const float*)d_in[12];
    float* out = (float*)d_out;

    const int n = in_sizes[2];       // 50000
    const int E = in_sizes[1] / 2;   // 800000
    const int* src = ei;
    const int* dst = ei + E;

    float* bufA; float* bufB;
    cudaGetSymbolAddress((void**)&bufA, g_bufA);
    cudaGetSymbolAddress((void**)&bufB, g_bufB);
    float* raw3 = bufA;
    float* agg3 = bufA + (size_t)NN * DOUT;

    const int TB = 256;
    int nb_n    = (n + TB - 1) / TB;
    int nb_e    = (E + TB - 1) / TB;
    int nb_gemm = (n + 127) / 128;
    int nb_sc128 = (int)(((long long)E * 32 + TB - 1) / TB);
    int nb_sc64  = (int)((((long long)(E + 1) / 2) * 32 + TB - 1) / TB);
    int nb_stats = 128;
    int nb_pool  = (n + POOL_CHUNK - 1) / POOL_CHUNK;

    // degree / norm
    k_init<<<nb_n, TB>>>(n);
    k_deg<<<nb_e, TB>>>(dst, E, n);
    k_dinv<<<nb_n, TB>>>(n);

    // ---- layer 1 ----
    k_gemm_mma<256, 128, false><<<nb_gemm, 256>>>(x, W1, bufA, bufB, n);
    k_scatter<128><<<nb_sc128, TB>>>(src, dst, bufA, bufB, E, n);
    k_bnzero<<<1, DHID>>>();
    k_bnstats<<<nb_stats, 256>>>(bufB, n);
    k_bnfinal<<<1, DHID>>>(g1, be1, (float)n);

    // ---- layer 2 (BN1+ReLU fused into X load; scaled written in-place) ----
    k_gemm_mma<128, 128, true><<<nb_gemm, 256>>>(bufB, W2, bufA, bufB, n);
    k_scatter<128><<<nb_sc128, TB>>>(src, dst, bufA, bufB, E, n);
    k_bnzero<<<1, DHID>>>();
    k_bnstats<<<nb_stats, 256>>>(bufB, n);
    k_bnfinal<<<1, DHID>>>(g2, be2, (float)n);

    // ---- layer 3 (BN2+ReLU fused) ----
    k_gemm_mma<128, 64, true><<<nb_gemm, 256>>>(bufB, W3, raw3, agg3, n);
    k_scatter<64><<<nb_sc64, TB>>>(src, dst, raw3, agg3, E, n);

    // ---- mean pool + bias ----
    k_pool<<<nb_pool, DOUT>>>(agg3, batch, n);
    k_final<<<1, NGRAPH * DOUT>>>(out, b3);
}

// round 7
// speedup vs baseline: 1.3772x; 1.0627x over previous
#include <cuda_runtime.h>
#include <cuda_bf16.h>
#include <math.h>
#include <stdint.h>

// ---------------- problem constants ----------------
#define NN 50000
#define DHID 128
#define DOUT 64
#define NGRAPH 16
#define BN_EPS 1e-5f
#define MAXK 256
#define NBSTAT 128

// ---------------- device scratch ----------------
__device__ __align__(16) float g_dinv[NN];
__device__ __align__(16) float g_bufA[NN * DHID];
__device__ __align__(16) float g_bufB[NN * DHID];
__device__ __align__(16) __nv_bfloat16 g_wth[MAXK * DHID];   // W^T hi, [N][K]
__device__ __align__(16) __nv_bfloat16 g_wtl[MAXK * DHID];   // W^T lo
__device__ __align__(16) float g_bnpart[NBSTAT][2 * DHID];
__device__ __align__(16) float g_bnsum[DHID];
__device__ __align__(16) float g_bnsq[DHID];
__device__ __align__(16) float g_pool[NGRAPH * DOUT];
__device__ __align__(16) float g_pcnt[NGRAPH];

// ---------------- init / degree / rsqrt ----------------
__global__ void k_init(int n) {
    int i = blockIdx.x * blockDim.x + threadIdx.x;
    if (i < n) g_dinv[i] = 1.0f;
    if (i < NGRAPH * DOUT) g_pool[i] = 0.0f;
    if (i < NGRAPH) g_pcnt[i] = 0.0f;
}

__global__ void k_deg(const int* __restrict__ dst, int e, int n) {
    int i = blockIdx.x * blockDim.x + threadIdx.x;
    if (i < e) {
        int d = dst[i];
        if ((unsigned)d < (unsigned)n) atomicAdd(&g_dinv[d], 1.0f);
    }
}

__global__ void k_dinv(int n) {
    int i = blockIdx.x * blockDim.x + threadIdx.x;
    if (i < n) g_dinv[i] = rsqrtf(g_dinv[i]);
}

// ---------------- W prep: fp32 [K][N] -> bf16 hi/lo transposed [N][K] -------
template <int K, int N>
__global__ void k_wprep(const float* __restrict__ W) {
    int i = blockIdx.x * blockDim.x + threadIdx.x;
    if (i >= K * N) return;
    int k = i / N, n = i % N;
    float v = W[i];
    __nv_bfloat16 h = __float2bfloat16(v);
    __nv_bfloat16 l = __float2bfloat16(v - __bfloat162float(h));
    g_wth[n * K + k] = h;
    g_wtl[n * K + k] = l;
}

// ---------------- bf16 mma ----------------
#define MMA_BF16(d, a, b0, b1)                                              \
    asm volatile(                                                           \
        "mma.sync.aligned.m16n8k16.row.col.f32.bf16.bf16.f32 "              \
        "{%0,%1,%2,%3}, {%4,%5,%6,%7}, {%8,%9}, {%0,%1,%2,%3};"             \
        : "+f"((d)[0]), "+f"((d)[1]), "+f"((d)[2]), "+f"((d)[3])            \
        : "r"((a)[0]), "r"((a)[1]), "r"((a)[2]), "r"((a)[3]),               \
          "r"(b0), "r"(b1))

// ---------------- tensor-core GEMM (3x bf16 split) + fused epilogues -------
// OUT_raw = T(X) @ W ; OUT_scaled = OUT_raw * dinv[row]^2
// 256 threads = 8 warps (4m x 2n); block tile 128 x NOUT; warp 32 x NOUT/2.
// Double-buffered smem, register prefetch, one sync per k-tile.
template <int KDIM, int NOUT, bool BNRELU>
__global__ void __launch_bounds__(256, 2)
k_gemm_bf16(const float* X, float* __restrict__ OUT_raw,
            float* OUT_scaled, int nrows) {
    constexpr int BM = 128, BK = 16, KS = 24;     // KS: 48B row stride
    constexpr int hN = NOUT / 2;
    constexpr int NT = hN / 8;                    // 8 or 4
    constexpr int MT = 2;
    constexpr int KT = KDIM / BK;
    constexpr int WL = (NOUT == 128) ? 8 : 4;     // W bf16 elems per thread

    __shared__ __nv_bfloat16 Xh[2][BM][KS], Xl[2][BM][KS];
    __shared__ __nv_bfloat16 Wh[2][NOUT][KS], Wl[2][NOUT][KS];

    const int tid = threadIdx.x;
    const int lane = tid & 31;
    const int wid = tid >> 5;
    const int wm = wid & 3, wn = wid >> 2;
    const int row0 = blockIdx.x * BM;

    const int xr = tid >> 1;                      // 0..127
    const int xkp = (tid & 1) * 8;                // 0 or 8
    const int wr = (NOUT == 128) ? (tid >> 1) : (tid >> 2);
    const int wkp = (NOUT == 128) ? (tid & 1) * 8 : (tid & 3) * 4;

    const int kc2 = (lane & 3) * 2;
    const int rfo = lane >> 2;

    float acc[MT][NT][4] = {};

    float xv[8];
    __nv_bfloat16 wvh[WL], wvl[WL];

    // ---- load tile kb into regs ----
    auto fetch = [&](int kb) {
        int row = row0 + xr;
#pragma unroll
        for (int i = 0; i < 2; i++) {
            float4 v = make_float4(0.f, 0.f, 0.f, 0.f);
            if (row < nrows)
                v = *reinterpret_cast<const float4*>(
                    &X[(size_t)row * KDIM + kb + xkp + i * 4]);
            xv[i * 4 + 0] = v.x; xv[i * 4 + 1] = v.y;
            xv[i * 4 + 2] = v.z; xv[i * 4 + 3] = v.w;
        }
        const __nv_bfloat16* ph = &g_wth[(size_t)wr * KDIM + kb + wkp];
        const __nv_bfloat16* pl = &g_wtl[(size_t)wr * KDIM + kb + wkp];
        if (WL == 8) {
            *reinterpret_cast<uint4*>(wvh) = *reinterpret_cast<const uint4*>(ph);
            *reinterpret_cast<uint4*>(wvl) = *reinterpret_cast<const uint4*>(pl);
        } else {
            *reinterpret_cast<uint2*>(wvh) = *reinterpret_cast<const uint2*>(ph);
            *reinterpret_cast<uint2*>(wvl) = *reinterpret_cast<const uint2*>(pl);
        }
    };

    // ---- transform + store regs into stage s ----
    auto stage = [&](int kb, int s) {
        __nv_bfloat16 hx[8], lx[8];
#pragma unroll
        for (int j = 0; j < 8; j++) {
            float v = xv[j];
            if (BNRELU)
                v = fmaxf(fmaf(v, g_bnsum[kb + xkp + j], g_bnsq[kb + xkp + j]), 0.f);
            __nv_bfloat16 h = __float2bfloat16(v);
            hx[j] = h;
            lx[j] = __float2bfloat16(v - __bfloat162float(h));
        }
        *reinterpret_cast<uint4*>(&Xh[s][xr][xkp]) = *reinterpret_cast<uint4*>(hx);
        *reinterpret_cast<uint4*>(&Xl[s][xr][xkp]) = *reinterpret_cast<uint4*>(lx);
        if (WL == 8) {
            *reinterpret_cast<uint4*>(&Wh[s][wr][wkp]) = *reinterpret_cast<uint4*>(wvh);
            *reinterpret_cast<uint4*>(&Wl[s][wr][wkp]) = *reinterpret_cast<uint4*>(wvl);
        } else {
            *reinterpret_cast<uint2*>(&Wh[s][wr][wkp]) = *reinterpret_cast<uint2*>(wvh);
            *reinterpret_cast<uint2*>(&Wl[s][wr][wkp]) = *reinterpret_cast<uint2*>(wvl);
        }
    };

    fetch(0);
    stage(0, 0);
    __syncthreads();

    for (int kt = 0; kt < KT; kt++) {
        const int s = kt & 1;
        const bool more = (kt + 1 < KT);
        if (more) fetch((kt + 1) * BK);

        // A fragments (hi, lo)
        unsigned ah[MT][4], al[MT][4];
#pragma unroll
        for (int mt = 0; mt < MT; mt++) {
            int ar = wm * 32 + mt * 16 + rfo;
            ah[mt][0] = *reinterpret_cast<const unsigned*>(&Xh[s][ar][kc2]);
            ah[mt][1] = *reinterpret_cast<const unsigned*>(&Xh[s][ar + 8][kc2]);
            ah[mt][2] = *reinterpret_cast<const unsigned*>(&Xh[s][ar][kc2 + 8]);
            ah[mt][3] = *reinterpret_cast<const unsigned*>(&Xh[s][ar + 8][kc2 + 8]);
            al[mt][0] = *reinterpret_cast<const unsigned*>(&Xl[s][ar][kc2]);
            al[mt][1] = *reinterpret_cast<const unsigned*>(&Xl[s][ar + 8][kc2]);
            al[mt][2] = *reinterpret_cast<const unsigned*>(&Xl[s][ar][kc2 + 8]);
            al[mt][3] = *reinterpret_cast<const unsigned*>(&Xl[s][ar + 8][kc2 + 8]);
        }
#pragma unroll
        for (int nt = 0; nt < NT; nt++) {
            int bn = wn * hN + nt * 8 + rfo;
            unsigned bh0 = *reinterpret_cast<const unsigned*>(&Wh[s][bn][kc2]);
            unsigned bh1 = *reinterpret_cast<const unsigned*>(&Wh[s][bn][kc2 + 8]);
            unsigned bl0 = *reinterpret_cast<const unsigned*>(&Wl[s][bn][kc2]);
            unsigned bl1 = *reinterpret_cast<const unsigned*>(&Wl[s][bn][kc2 + 8]);
#pragma unroll
            for (int mt = 0; mt < MT; mt++) MMA_BF16(acc[mt][nt], ah[mt], bh0, bh1);
#pragma unroll
            for (int mt = 0; mt < MT; mt++) MMA_BF16(acc[mt][nt], ah[mt], bl0, bl1);
#pragma unroll
            for (int mt = 0; mt < MT; mt++) MMA_BF16(acc[mt][nt], al[mt], bh0, bh1);
        }

        if (more) stage((kt + 1) * BK, s ^ 1);
        __syncthreads();
    }

    // ---- epilogue: raw + dinv^2-scaled ----
#pragma unroll
    for (int mt = 0; mt < MT; mt++) {
        int r0 = row0 + wm * 32 + mt * 16 + rfo;
        int r1 = r0 + 8;
        float d0 = 0.f, d1 = 0.f;
        if (r0 < nrows) { d0 = g_dinv[r0]; d0 *= d0; }
        if (r1 < nrows) { d1 = g_dinv[r1]; d1 *= d1; }
#pragma unroll
        for (int nt = 0; nt < NT; nt++) {
            int col = wn * hN + nt * 8 + (lane & 3) * 2;
            if (r0 < nrows) {
                float2 raw = make_float2(acc[mt][nt][0], acc[mt][nt][1]);
                size_t off = (size_t)r0 * NOUT + col;
                *reinterpret_cast<float2*>(&OUT_raw[off]) = raw;
                *reinterpret_cast<float2*>(&OUT_scaled[off]) =
                    make_float2(raw.x * d0, raw.y * d0);
            }
            if (r1 < nrows) {
                float2 raw = make_float2(acc[mt][nt][2], acc[mt][nt][3]);
                size_t off = (size_t)r1 * NOUT + col;
                *reinterpret_cast<float2*>(&OUT_raw[off]) = raw;
                *reinterpret_cast<float2*>(&OUT_scaled[off]) =
                    make_float2(raw.x * d1, raw.y * d1);
            }
        }
    }
}

// ---------------- edge scatter: out[d] += h[s] * dinv[s]*dinv[d] ------------
template <int NOUT>
__global__ void k_scatter(const int* __restrict__ src, const int* __restrict__ dst,
                          const float* __restrict__ h, float* __restrict__ out,
                          int e_total, int n) {
    constexpr int LPE = NOUT / 4;
    constexpr int EPW = 32 / LPE;
    int warp = (blockIdx.x * blockDim.x + threadIdx.x) >> 5;
    int lane = threadIdx.x & 31;
    int e = warp * EPW + lane / LPE;
    if (e >= e_total) return;
    int s = src[e];
    int d = dst[e];
    if ((unsigned)s >= (unsigned)n || (unsigned)d >= (unsigned)n) return;
    float w = g_dinv[s] * g_dinv[d];
    int c = (lane % LPE) * 4;
    float4 v = *reinterpret_cast<const float4*>(&h[(size_t)s * NOUT + c]);
    unsigned long long gp =
        (unsigned long long)__cvta_generic_to_global(&out[(size_t)d * NOUT + c]);
    asm volatile("red.global.add.v4.f32 [%0], {%1,%2,%3,%4};"
                 :: "l"(gp), "f"(v.x * w), "f"(v.y * w), "f"(v.z * w), "f"(v.w * w)
                 : "memory");
}

// ---------------- BN: per-block partials (no zero pass, no global atomics) --
__global__ void k_bnstats(const float* __restrict__ a, int n) {
    __shared__ float ssum[DHID], ssq[DHID];
    int tid = threadIdx.x;
    if (tid < DHID) { ssum[tid] = 0.0f; ssq[tid] = 0.0f; }
    __syncthreads();

    int c = (tid & 31) * 4;
    int rp = tid >> 5;
    float s0 = 0, s1 = 0, s2 = 0, s3 = 0;
    float q0 = 0, q1 = 0, q2 = 0, q3 = 0;
    int stride = gridDim.x * 8;
    for (int r = blockIdx.x * 8 + rp; r < n; r += stride) {
        float4 v = *reinterpret_cast<const float4*>(&a[(size_t)r * DHID + c]);
        s0 += v.x; q0 += v.x * v.x;
        s1 += v.y; q1 += v.y * v.y;
        s2 += v.z; q2 += v.z * v.z;
        s3 += v.w; q3 += v.w * v.w;
    }
    atomicAdd(&ssum[c + 0], s0); atomicAdd(&ssq[c + 0], q0);
    atomicAdd(&ssum[c + 1], s1); atomicAdd(&ssq[c + 1], q1);
    atomicAdd(&ssum[c + 2], s2); atomicAdd(&ssq[c + 2], q2);
    atomicAdd(&ssum[c + 3], s3); atomicAdd(&ssq[c + 3], q3);
    __syncthreads();
    if (tid < DHID) {
        g_bnpart[blockIdx.x][tid] = ssum[tid];
        g_bnpart[blockIdx.x][DHID + tid] = ssq[tid];
    }
}

__global__ void k_bnfinal(const float* __restrict__ gam, const float* __restrict__ bet, float n) {
    int c = threadIdx.x;  // 128
    float s = 0.0f, q = 0.0f;
#pragma unroll 4
    for (int b = 0; b < NBSTAT; b++) {
        s += g_bnpart[b][c];
        q += g_bnpart[b][DHID + c];
    }
    float mu = s / n;
    float var = q / n - mu * mu;
    float sc = rsqrtf(var + BN_EPS) * gam[c];
    g_bnsum[c] = sc;
    g_bnsq[c] = bet[c] - mu * sc;
}

// ---------------- pool: batch sorted -> run-length accumulate ----------------
#define POOL_CHUNK 128
__global__ void k_pool(const float* __restrict__ h, const int* __restrict__ batch, int n) {
    int col = threadIdx.x;  // 64
    int r0 = blockIdx.x * POOL_CHUNK;
    if (r0 >= n) return;
    int r1 = min(r0 + POOL_CHUNK, n);
    int cur = batch[r0] & (NGRAPH - 1);
    float acc = 0.0f, cacc = 0.0f;
    for (int r = r0; r < r1; r++) {
        int g = batch[r] & (NGRAPH - 1);
        if (g != cur) {
            atomicAdd(&g_pool[cur * DOUT + col], acc);
            if (col == 0) atomicAdd(&g_pcnt[cur], cacc);
            acc = 0.0f; cacc = 0.0f; cur = g;
        }
        acc += h[(size_t)r * DOUT + col];
        cacc += 1.0f;
    }
    atomicAdd(&g_pool[cur * DOUT + col], acc);
    if (col == 0) atomicAdd(&g_pcnt[cur], cacc);
}

__global__ void k_final(float* __restrict__ out, const float* __restrict__ b3) {
    int t = threadIdx.x;  // 1024
    int g = t / DOUT;
    int c = t % DOUT;
    float cnt = g_pcnt[g];
    out[t] = (cnt > 0.0f) ? (g_pool[t] / cnt + b3[c]) : 0.0f;
}

// ============================================================================
extern "C" void kernel_launch(void* const* d_in, const int* in_sizes, int n_in,
                              void* d_out, int out_size) {
    const float* x     = (const float*)d_in[0];
    const int*   ei    = (const int*)d_in[1];   // int64 coerced to int32
    const int*   batch = (const int*)d_in[2];
    const float* W1    = (const float*)d_in[3];
    const float* W2    = (const float*)d_in[5];
    const float* W3    = (const float*)d_in[7];
    const float* b3    = (const float*)d_in[8];
    const float* g1    = (const float*)d_in[9];
    const float* be1   = (const float*)d_in[10];
    const float* g2    = (const float*)d_in[11];
    const float* be2   = (const float*)d_in[12];
    float* out = (float*)d_out;

    const int n = in_sizes[2];       // 50000
    const int E = in_sizes[1] / 2;   // 800000
    const int* src = ei;
    const int* dst = ei + E;

    float* bufA; float* bufB;
    cudaGetSymbolAddress((void**)&bufA, g_bufA);
    cudaGetSymbolAddress((void**)&bufB, g_bufB);
    float* raw3 = bufA;
    float* agg3 = bufA + (size_t)NN * DOUT;

    const int TB = 256;
    int nb_n    = (n + TB - 1) / TB;
    int nb_e    = (E + TB - 1) / TB;
    int nb_gemm = (n + 127) / 128;
    int nb_sc128 = (int)(((long long)E * 32 + TB - 1) / TB);
    int nb_sc64  = (int)((((long long)(E + 1) / 2) * 32 + TB - 1) / TB);
    int nb_pool  = (n + POOL_CHUNK - 1) / POOL_CHUNK;

    // degree / norm
    k_init<<<nb_n, TB>>>(n);
    k_deg<<<nb_e, TB>>>(dst, E, n);
    k_dinv<<<nb_n, TB>>>(n);

    // ---- layer 1 ----
    k_wprep<256, 128><<<(256 * 128 + TB - 1) / TB, TB>>>(W1);
    k_gemm_bf16<256, 128, false><<<nb_gemm, 256>>>(x, bufA, bufB, n);
    k_scatter<128><<<nb_sc128, TB>>>(src, dst, bufA, bufB, E, n);
    k_bnstats<<<NBSTAT, 256>>>(bufB, n);
    k_bnfinal<<<1, DHID>>>(g1, be1, (float)n);

    // ---- layer 2 (BN1+ReLU fused into X load; scaled written in-place) ----
    k_wprep<128, 128><<<(128 * 128 + TB - 1) / TB, TB>>>(W2);
    k_gemm_bf16<128, 128, true><<<nb_gemm, 256>>>(bufB, bufA, bufB, n);
    k_scatter<128><<<nb_sc128, TB>>>(src, dst, bufA, bufB, E, n);
    k_bnstats<<<NBSTAT, 256>>>(bufB, n);
    k_bnfinal<<<1, DHID>>>(g2, be2, (float)n);

    // ---- layer 3 (BN2+ReLU fused) ----
    k_wprep<128, 64><<<(128 * 64 + TB - 1) / TB, TB>>>(W3);
    k_gemm_bf16<128, 64, true><<<nb_gemm, 256>>>(bufB, raw3, agg3, n);
    k_scatter<64><<<nb_sc64, TB>>>(src, dst, raw3, agg3, E, n);

    // ---- mean pool + bias ----
    k_pool<<<nb_pool, DOUT>>>(agg3, batch, n);
    k_final<<<1, NGRAPH * DOUT>>>(out, b3);
}

// round 8
// speedup vs baseline: 1.6805x; 1.2202x over previous
#include <cuda_runtime.h>
#include <cuda_bf16.h>
#include <math.h>
#include <stdint.h>

// ---------------- problem constants ----------------
#define NN 50000
#define EMAX 800000
#define DHID 128
#define DOUT 64
#define NGRAPH 16
#define BN_EPS 1e-5f
#define MAXK 256

// ---------------- device scratch ----------------
__device__ __align__(16) float g_dinv[NN];
__device__ __align__(16) int   g_cnt[NN];        // counts, then fill cursor
__device__ __align__(16) int   g_off[NN + 1];    // CSR offsets
__device__ __align__(16) int2  g_edges[EMAX];    // (src, bitcast w)
__device__ __align__(16) float g_bufA[NN * DHID];
__device__ __align__(16) float g_bufB[NN * DHID];
__device__ __align__(16) __nv_bfloat16 g_wth[MAXK * DHID];   // W^T hi [N][K]
__device__ __align__(16) __nv_bfloat16 g_wtl[MAXK * DHID];   // W^T lo
__device__ __align__(16) float g_stat_s[DHID];   // BN accumulation
__device__ __align__(16) float g_stat_q[DHID];
__device__ __align__(16) float g_bnsum[DHID];    // BN scale (by k)
__device__ __align__(16) float g_bnsq[DHID];     // BN shift (by k)
__device__ __align__(16) float g_pool[NGRAPH * DOUT];
__device__ __align__(16) float g_pcnt[NGRAPH];

// ---------------- init ----------------
__global__ void k_init(int n) {
    int i = blockIdx.x * blockDim.x + threadIdx.x;
    if (i < n) g_cnt[i] = 0;
    if (i < DHID) { g_stat_s[i] = 0.0f; g_stat_q[i] = 0.0f; }
    if (i < NGRAPH * DOUT) g_pool[i] = 0.0f;
    if (i < NGRAPH) g_pcnt[i] = 0.0f;
}

__global__ void k_cnt(const int* __restrict__ dst, int e, int n) {
    int i = blockIdx.x * blockDim.x + threadIdx.x;
    if (i < e) {
        int d = dst[i];
        if ((unsigned)d < (unsigned)n) atomicAdd(&g_cnt[d], 1);
    }
}

// deg = cnt + 1 (self loop)
__global__ void k_dinv(int n) {
    int i = blockIdx.x * blockDim.x + threadIdx.x;
    if (i < n) g_dinv[i] = rsqrtf((float)g_cnt[i] + 1.0f);
}

// single-block exclusive scan: g_cnt(counts) -> g_off(offsets), g_cnt(cursor)
__global__ void k_scan(int n) {
    __shared__ int tot[1024];
    int t = threadIdx.x;
    int chunk = (n + 1023) / 1024;
    int lo = t * chunk, hi = min(lo + chunk, n);
    int s = 0;
    for (int i = lo; i < hi; i++) s += g_cnt[i];
    tot[t] = s;
    __syncthreads();
    // Hillis-Steele inclusive scan over 1024 partials
    for (int d = 1; d < 1024; d <<= 1) {
        int v = (t >= d) ? tot[t - d] : 0;
        __syncthreads();
        tot[t] += v;
        __syncthreads();
    }
    int run = (t > 0) ? tot[t - 1] : 0;   // exclusive base
    for (int i = lo; i < hi; i++) {
        int c = g_cnt[i];
        g_off[i] = run;
        g_cnt[i] = run;    // cursor for fill
        run += c;
    }
    if (lo < n && hi == n) g_off[n] = run;
}

__global__ void k_fill(const int* __restrict__ src, const int* __restrict__ dst,
                       int e, int n) {
    int i = blockIdx.x * blockDim.x + threadIdx.x;
    if (i >= e) return;
    int s = src[i], d = dst[i];
    if ((unsigned)s >= (unsigned)n || (unsigned)d >= (unsigned)n) return;
    float w = g_dinv[s] * g_dinv[d];
    int pos = atomicAdd(&g_cnt[d], 1);
    g_edges[pos] = make_int2(s, __float_as_int(w));
}

// ---------------- W prep: fp32 [K][N] -> bf16 hi/lo transposed [N][K] -------
template <int K, int N>
__global__ void k_wprep(const float* __restrict__ W) {
    int i = blockIdx.x * blockDim.x + threadIdx.x;
    if (i >= K * N) return;
    int k = i / N, n = i % N;
    float v = W[i];
    __nv_bfloat16 h = __float2bfloat16(v);
    __nv_bfloat16 l = __float2bfloat16(v - __bfloat162float(h));
    g_wth[n * K + k] = h;
    g_wtl[n * K + k] = l;
}

// ---------------- bf16 mma ----------------
#define MMA_BF16(d, a, b0, b1)                                              \
    asm volatile(                                                           \
        "mma.sync.aligned.m16n8k16.row.col.f32.bf16.bf16.f32 "              \
        "{%0,%1,%2,%3}, {%4,%5,%6,%7}, {%8,%9}, {%0,%1,%2,%3};"             \
        : "+f"((d)[0]), "+f"((d)[1]), "+f"((d)[2]), "+f"((d)[3])            \
        : "r"((a)[0]), "r"((a)[1]), "r"((a)[2]), "r"((a)[3]),               \
          "r"(b0), "r"(b1))

// ---------------- tensor-core GEMM (3x bf16 split), raw output only --------
template <int KDIM, int NOUT, bool BNRELU>
__global__ void __launch_bounds__(256, 2)
k_gemm_bf16(const float* X, float* __restrict__ OUT, int nrows) {
    constexpr int BM = 128, BK = 16, KS = 24;
    constexpr int hN = NOUT / 2;
    constexpr int NT = hN / 8;
    constexpr int MT = 2;
    constexpr int KT = KDIM / BK;
    constexpr int WL = (NOUT == 128) ? 8 : 4;

    __shared__ __nv_bfloat16 Xh[2][BM][KS], Xl[2][BM][KS];
    __shared__ __nv_bfloat16 Wh[2][NOUT][KS], Wl[2][NOUT][KS];

    const int tid = threadIdx.x;
    const int lane = tid & 31;
    const int wid = tid >> 5;
    const int wm = wid & 3, wn = wid >> 2;
    const int row0 = blockIdx.x * BM;

    const int xr = tid >> 1;
    const int xkp = (tid & 1) * 8;
    const int wr = (NOUT == 128) ? (tid >> 1) : (tid >> 2);
    const int wkp = (NOUT == 128) ? (tid & 1) * 8 : (tid & 3) * 4;
    const int kc2 = (lane & 3) * 2;
    const int rfo = lane >> 2;

    float acc[MT][NT][4] = {};
    float xv[8];
    __nv_bfloat16 wvh[WL], wvl[WL];

    auto fetch = [&](int kb) {
        int row = row0 + xr;
#pragma unroll
        for (int i = 0; i < 2; i++) {
            float4 v = make_float4(0.f, 0.f, 0.f, 0.f);
            if (row < nrows)
                v = *reinterpret_cast<const float4*>(
                    &X[(size_t)row * KDIM + kb + xkp + i * 4]);
            xv[i * 4 + 0] = v.x; xv[i * 4 + 1] = v.y;
            xv[i * 4 + 2] = v.z; xv[i * 4 + 3] = v.w;
        }
        const __nv_bfloat16* ph = &g_wth[(size_t)wr * KDIM + kb + wkp];
        const __nv_bfloat16* pl = &g_wtl[(size_t)wr * KDIM + kb + wkp];
        if (WL == 8) {
            *reinterpret_cast<uint4*>(wvh) = *reinterpret_cast<const uint4*>(ph);
            *reinterpret_cast<uint4*>(wvl) = *reinterpret_cast<const uint4*>(pl);
        } else {
            *reinterpret_cast<uint2*>(wvh) = *reinterpret_cast<const uint2*>(ph);
            *reinterpret_cast<uint2*>(wvl) = *reinterpret_cast<const uint2*>(pl);
        }
    };

    auto stage = [&](int kb, int s) {
        __nv_bfloat16 hx[8], lx[8];
#pragma unroll
        for (int j = 0; j < 8; j++) {
            float v = xv[j];
            if (BNRELU)
                v = fmaxf(fmaf(v, g_bnsum[kb + xkp + j], g_bnsq[kb + xkp + j]), 0.f);
            __nv_bfloat16 h = __float2bfloat16(v);
            hx[j] = h;
            lx[j] = __float2bfloat16(v - __bfloat162float(h));
        }
        *reinterpret_cast<uint4*>(&Xh[s][xr][xkp]) = *reinterpret_cast<uint4*>(hx);
        *reinterpret_cast<uint4*>(&Xl[s][xr][xkp]) = *reinterpret_cast<uint4*>(lx);
        if (WL == 8) {
            *reinterpret_cast<uint4*>(&Wh[s][wr][wkp]) = *reinterpret_cast<uint4*>(wvh);
            *reinterpret_cast<uint4*>(&Wl[s][wr][wkp]) = *reinterpret_cast<uint4*>(wvl);
        } else {
            *reinterpret_cast<uint2*>(&Wh[s][wr][wkp]) = *reinterpret_cast<uint2*>(wvh);
            *reinterpret_cast<uint2*>(&Wl[s][wr][wkp]) = *reinterpret_cast<uint2*>(wvl);
        }
    };

    fetch(0);
    stage(0, 0);
    __syncthreads();

    for (int kt = 0; kt < KT; kt++) {
        const int s = kt & 1;
        const bool more = (kt + 1 < KT);
        if (more) fetch((kt + 1) * BK);

        unsigned ah[MT][4], al[MT][4];
#pragma unroll
        for (int mt = 0; mt < MT; mt++) {
            int ar = wm * 32 + mt * 16 + rfo;
            ah[mt][0] = *reinterpret_cast<const unsigned*>(&Xh[s][ar][kc2]);
            ah[mt][1] = *reinterpret_cast<const unsigned*>(&Xh[s][ar + 8][kc2]);
            ah[mt][2] = *reinterpret_cast<const unsigned*>(&Xh[s][ar][kc2 + 8]);
            ah[mt][3] = *reinterpret_cast<const unsigned*>(&Xh[s][ar + 8][kc2 + 8]);
            al[mt][0] = *reinterpret_cast<const unsigned*>(&Xl[s][ar][kc2]);
            al[mt][1] = *reinterpret_cast<const unsigned*>(&Xl[s][ar + 8][kc2]);
            al[mt][2] = *reinterpret_cast<const unsigned*>(&Xl[s][ar][kc2 + 8]);
            al[mt][3] = *reinterpret_cast<const unsigned*>(&Xl[s][ar + 8][kc2 + 8]);
        }
#pragma unroll
        for (int nt = 0; nt < NT; nt++) {
            int bn = wn * hN + nt * 8 + rfo;
            unsigned bh0 = *reinterpret_cast<const unsigned*>(&Wh[s][bn][kc2]);
            unsigned bh1 = *reinterpret_cast<const unsigned*>(&Wh[s][bn][kc2 + 8]);
            unsigned bl0 = *reinterpret_cast<const unsigned*>(&Wl[s][bn][kc2]);
            unsigned bl1 = *reinterpret_cast<const unsigned*>(&Wl[s][bn][kc2 + 8]);
#pragma unroll
            for (int mt = 0; mt < MT; mt++) MMA_BF16(acc[mt][nt], ah[mt], bh0, bh1);
#pragma unroll
            for (int mt = 0; mt < MT; mt++) MMA_BF16(acc[mt][nt], ah[mt], bl0, bl1);
#pragma unroll
            for (int mt = 0; mt < MT; mt++) MMA_BF16(acc[mt][nt], al[mt], bh0, bh1);
        }

        if (more) stage((kt + 1) * BK, s ^ 1);
        __syncthreads();
    }

#pragma unroll
    for (int mt = 0; mt < MT; mt++) {
        int r0 = row0 + wm * 32 + mt * 16 + rfo;
        int r1 = r0 + 8;
#pragma unroll
        for (int nt = 0; nt < NT; nt++) {
            int col = wn * hN + nt * 8 + (lane & 3) * 2;
            if (r0 < nrows)
                *reinterpret_cast<float2*>(&OUT[(size_t)r0 * NOUT + col]) =
                    make_float2(acc[mt][nt][0], acc[mt][nt][1]);
            if (r1 < nrows)
                *reinterpret_cast<float2*>(&OUT[(size_t)r1 * NOUT + col]) =
                    make_float2(acc[mt][nt][2], acc[mt][nt][3]);
        }
    }
}

// ---------------- CSR aggregation (gather): out[d] = h[d]*dinv^2 + sum ------
// warp-per-node (NOUT=128) or half-warp-per-node (NOUT=64).
// Optionally accumulates BN stats (sum, sumsq) for the output rows.
template <int NOUT, bool BNSTAT>
__global__ void __launch_bounds__(256)
k_aggr(const float* __restrict__ h, float* __restrict__ out, int n) {
    constexpr int LPN = NOUT / 4;        // lanes per node (32 or 16)
    constexpr int NPW = 32 / LPN;        // nodes per warp (1 or 2)
    constexpr int NPB = 8 * NPW;         // nodes per block
    __shared__ float ss[BNSTAT ? DHID : 1], sq[BNSTAT ? DHID : 1];

    int tid = threadIdx.x;
    int warp = tid >> 5, lane = tid & 31;
    if (BNSTAT) {
        if (tid < NOUT) { ss[tid] = 0.0f; sq[tid] = 0.0f; }
        __syncthreads();
    }

    int node = blockIdx.x * NPB + warp * NPW + lane / LPN;
    int c = (lane % LPN) * 4;
    float4 acc = make_float4(0.f, 0.f, 0.f, 0.f);
    bool active = (node < n);

    if (active) {
        float di = g_dinv[node];
        di *= di;
        float4 v = *reinterpret_cast<const float4*>(&h[(size_t)node * NOUT + c]);
        acc = make_float4(v.x * di, v.y * di, v.z * di, v.w * di);

        int i = g_off[node], e1 = g_off[node + 1];
        // 2-way software pipeline for MLP
        for (; i + 2 <= e1; i += 2) {
            int2 ea = g_edges[i], eb = g_edges[i + 1];
            float wa = __int_as_float(ea.y), wb = __int_as_float(eb.y);
            float4 va = *reinterpret_cast<const float4*>(&h[(size_t)ea.x * NOUT + c]);
            float4 vb = *reinterpret_cast<const float4*>(&h[(size_t)eb.x * NOUT + c]);
            acc.x = fmaf(va.x, wa, acc.x); acc.y = fmaf(va.y, wa, acc.y);
            acc.z = fmaf(va.z, wa, acc.z); acc.w = fmaf(va.w, wa, acc.w);
            acc.x = fmaf(vb.x, wb, acc.x); acc.y = fmaf(vb.y, wb, acc.y);
            acc.z = fmaf(vb.z, wb, acc.z); acc.w = fmaf(vb.w, wb, acc.w);
        }
        if (i < e1) {
            int2 e = g_edges[i];
            float w = __int_as_float(e.y);
            float4 v2 = *reinterpret_cast<const float4*>(&h[(size_t)e.x * NOUT + c]);
            acc.x = fmaf(v2.x, w, acc.x); acc.y = fmaf(v2.y, w, acc.y);
            acc.z = fmaf(v2.z, w, acc.z); acc.w = fmaf(v2.w, w, acc.w);
        }
        *reinterpret_cast<float4*>(&out[(size_t)node * NOUT + c]) = acc;
    }

    if (BNSTAT) {
        if (active) {
            atomicAdd(&ss[c + 0], acc.x); atomicAdd(&sq[c + 0], acc.x * acc.x);
            atomicAdd(&ss[c + 1], acc.y); atomicAdd(&sq[c + 1], acc.y * acc.y);
            atomicAdd(&ss[c + 2], acc.z); atomicAdd(&sq[c + 2], acc.z * acc.z);
            atomicAdd(&ss[c + 3], acc.w); atomicAdd(&sq[c + 3], acc.w * acc.w);
        }
        __syncthreads();
        if (tid < NOUT) {
            atomicAdd(&g_stat_s[tid], ss[tid]);
            atomicAdd(&g_stat_q[tid], sq[tid]);
        }
    }
}

// ---------------- BN finalize: stats -> (scale, shift); re-zero stats -------
__global__ void k_bnfinal(const float* __restrict__ gam, const float* __restrict__ bet, float n) {
    int c = threadIdx.x;  // 128
    float s = g_stat_s[c], q = g_stat_q[c];
    float mu = s / n;
    float var = q / n - mu * mu;
    float sc = rsqrtf(var + BN_EPS) * gam[c];
    g_bnsum[c] = sc;
    g_bnsq[c] = bet[c] - mu * sc;
    g_stat_s[c] = 0.0f;    // ready for next layer / next graph replay
    g_stat_q[c] = 0.0f;
}

// ---------------- pool: batch sorted -> run-length accumulate ----------------
#define POOL_CHUNK 128
__global__ void k_pool(const float* __restrict__ h, const int* __restrict__ batch, int n) {
    int col = threadIdx.x;  // 64
    int r0 = blockIdx.x * POOL_CHUNK;
    if (r0 >= n) return;
    int r1 = min(r0 + POOL_CHUNK, n);
    int cur = batch[r0] & (NGRAPH - 1);
    float acc = 0.0f, cacc = 0.0f;
    for (int r = r0; r < r1; r++) {
        int g = batch[r] & (NGRAPH - 1);
        if (g != cur) {
            atomicAdd(&g_pool[cur * DOUT + col], acc);
            if (col == 0) atomicAdd(&g_pcnt[cur], cacc);
            acc = 0.0f; cacc = 0.0f; cur = g;
        }
        acc += h[(size_t)r * DOUT + col];
        cacc += 1.0f;
    }
    atomicAdd(&g_pool[cur * DOUT + col], acc);
    if (col == 0) atomicAdd(&g_pcnt[cur], cacc);
}

__global__ void k_final(float* __restrict__ out, const float* __restrict__ b3) {
    int t = threadIdx.x;  // 1024
    int g = t / DOUT;
    int c = t % DOUT;
    float cnt = g_pcnt[g];
    out[t] = (cnt > 0.0f) ? (g_pool[t] / cnt + b3[c]) : 0.0f;
}

// ============================================================================
extern "C" void kernel_launch(void* const* d_in, const int* in_sizes, int n_in,
                              void* d_out, int out_size) {
    const float* x     = (const float*)d_in[0];
    const int*   ei    = (const int*)d_in[1];   // int64 coerced to int32
    const int*   batch = (const int*)d_in[2];
    const float* W1    = (const float*)d_in[3];
    const float* W2    = (const float*)d_in[5];
    const float* W3    = (const float*)d_in[7];
    const float* b3    = (const float*)d_in[8];
    const float* g1    = (const float*)d_in[9];
    const float* be1   = (const float*)d_in[10];
    const float* g2    = (const float*)d_in[11];
    const float* be2   = (const float*)d_in[12];
    float* out = (float*)d_out;

    const int n = in_sizes[2];       // 50000
    const int E = in_sizes[1] / 2;   // 800000
    const int* src = ei;
    const int* dst = ei + E;

    float* bufA; float* bufB;
    cudaGetSymbolAddress((void**)&bufA, g_bufA);
    cudaGetSymbolAddress((void**)&bufB, g_bufB);
    float* raw3 = bufA;                       // layer-3 gemm out (stride 64)
    float* agg3 = bufA + (size_t)NN * DOUT;   // layer-3 aggregation out

    const int TB = 256;
    int nb_n    = (n + TB - 1) / TB;
    int nb_e    = (E + TB - 1) / TB;
    int nb_gemm = (n + 127) / 128;
    int nb_ag128 = (n + 7) / 8;      // 8 nodes/block
    int nb_ag64  = (n + 15) / 16;    // 16 nodes/block
    int nb_pool  = (n + POOL_CHUNK - 1) / POOL_CHUNK;

    // ---- graph preprocessing: degree, dinv, CSR ----
    k_init<<<nb_n, TB>>>(n);
    k_cnt<<<nb_e, TB>>>(dst, E, n);
    k_dinv<<<nb_n, TB>>>(n);
    k_scan<<<1, 1024>>>(n);
    k_fill<<<nb_e, TB>>>(src, dst, E, n);

    // ---- layer 1 ----
    k_wprep<256, 128><<<(256 * 128 + TB - 1) / TB, TB>>>(W1);
    k_gemm_bf16<256, 128, false><<<nb_gemm, 256>>>(x, bufA, n);
    k_aggr<128, true><<<nb_ag128, 256>>>(bufA, bufB, n);
    k_bnfinal<<<1, DHID>>>(g1, be1, (float)n);

    // ---- layer 2 (BN1+ReLU fused into gemm X load) ----
    k_wprep<128, 128><<<(128 * 128 + TB - 1) / TB, TB>>>(W2);
    k_gemm_bf16<128, 128, true><<<nb_gemm, 256>>>(bufB, bufA, n);
    k_aggr<128, true><<<nb_ag128, 256>>>(bufA, bufB, n);
    k_bnfinal<<<1, DHID>>>(g2, be2, (float)n);

    // ---- layer 3 (BN2+ReLU fused) ----
    k_wprep<128, 64><<<(128 * 64 + TB - 1) / TB, TB>>>(W3);
    k_gemm_bf16<128, 64, true><<<nb_gemm, 256>>>(bufB, raw3, n);
    k_aggr<64, false><<<nb_ag64, 256>>>(raw3, agg3, n);

    // ---- mean pool + bias ----
    k_pool<<<nb_pool, DOUT>>>(agg3, batch, n);
    k_final<<<1, NGRAPH * DOUT>>>(out, b3);
}

// round 9
// speedup vs baseline: 2.0347x; 1.2108x over previous
#include <cuda_runtime.h>
#include <cuda_bf16.h>
#include <math.h>
#include <stdint.h>

// ---------------- problem constants ----------------
#define NN 50000
#define EMAX 800000
#define DHID 128
#define DOUT 64
#define NGRAPH 16
#define BN_EPS 1e-5f
#define MAXK 256
#define SCAN_B 256

// ---------------- device scratch ----------------
__device__ __align__(16) float g_dinv[NN];
__device__ __align__(16) int   g_cnt[NN];        // counts, then fill cursor
__device__ __align__(16) int   g_off[NN + 1];    // CSR offsets
__device__ __align__(16) int   g_bsum[SCAN_B];   // scan block partials
__device__ __align__(16) int2  g_edges[EMAX];    // (src, bitcast w)
__device__ __align__(16) float g_bufA[NN * DHID];
__device__ __align__(16) float g_bufB[NN * DHID];
__device__ __align__(16) __nv_bfloat16 g_wth[MAXK * DHID];   // W^T hi [N][K]
__device__ __align__(16) __nv_bfloat16 g_wtl[MAXK * DHID];   // W^T lo
__device__ __align__(16) float g_stat_s[DHID];   // BN accumulation
__device__ __align__(16) float g_stat_q[DHID];
__device__ __align__(16) float g_bnsum[DHID];    // BN scale (by k)
__device__ __align__(16) float g_bnsq[DHID];     // BN shift (by k)
__device__ __align__(16) float g_pool[NGRAPH * DOUT];
__device__ __align__(16) float g_pcnt[NGRAPH];

// ---------------- init ----------------
__global__ void k_init(int n) {
    int i = blockIdx.x * blockDim.x + threadIdx.x;
    if (i < n) g_cnt[i] = 0;
    if (i < DHID) { g_stat_s[i] = 0.0f; g_stat_q[i] = 0.0f; }
    if (i < NGRAPH * DOUT) g_pool[i] = 0.0f;
    if (i < NGRAPH) g_pcnt[i] = 0.0f;
}

__global__ void k_cnt(const int* __restrict__ dst, int e, int n) {
    int i = blockIdx.x * blockDim.x + threadIdx.x;
    if (i < e) {
        int d = dst[i];
        if ((unsigned)d < (unsigned)n) atomicAdd(&g_cnt[d], 1);
    }
}

// deg = cnt + 1 (self loop)
__global__ void k_dinv(int n) {
    int i = blockIdx.x * blockDim.x + threadIdx.x;
    if (i < n) g_dinv[i] = rsqrtf((float)g_cnt[i] + 1.0f);
}

// ---------------- 3-phase parallel exclusive scan over g_cnt ----------------
// A: per-block reduce -> g_bsum[b]
__global__ void k_scanA(int n) {
    __shared__ int sh[SCAN_B];
    int t = threadIdx.x;
    int i = blockIdx.x * SCAN_B + t;
    sh[t] = (i < n) ? g_cnt[i] : 0;
    __syncthreads();
#pragma unroll
    for (int d = SCAN_B / 2; d > 0; d >>= 1) {
        if (t < d) sh[t] += sh[t + d];
        __syncthreads();
    }
    if (t == 0) g_bsum[blockIdx.x] = sh[0];
}

// B: single block scans the (<=256) partials -> exclusive bases; total -> g_off[n]
__global__ void k_scanB(int nblocks, int n) {
    __shared__ int sh[SCAN_B];
    int t = threadIdx.x;
    int v = (t < nblocks) ? g_bsum[t] : 0;
    sh[t] = v;
    __syncthreads();
#pragma unroll
    for (int d = 1; d < SCAN_B; d <<= 1) {
        int x = (t >= d) ? sh[t - d] : 0;
        __syncthreads();
        sh[t] += x;
        __syncthreads();
    }
    if (t < nblocks) g_bsum[t] = sh[t] - v;       // exclusive base
    if (t == SCAN_B - 1) g_off[n] = sh[t];        // grand total
}

// C: per-block exclusive scan + base -> g_off[i], cursor g_cnt[i]
__global__ void k_scanC(int n) {
    __shared__ int sh[SCAN_B];
    int t = threadIdx.x;
    int i = blockIdx.x * SCAN_B + t;
    int v = (i < n) ? g_cnt[i] : 0;
    sh[t] = v;
    __syncthreads();
#pragma unroll
    for (int d = 1; d < SCAN_B; d <<= 1) {
        int x = (t >= d) ? sh[t - d] : 0;
        __syncthreads();
        sh[t] += x;
        __syncthreads();
    }
    if (i < n) {
        int off = g_bsum[blockIdx.x] + sh[t] - v;
        g_off[i] = off;
        g_cnt[i] = off;
    }
}

__global__ void k_fill(const int* __restrict__ src, const int* __restrict__ dst,
                       int e, int n) {
    int i = blockIdx.x * blockDim.x + threadIdx.x;
    if (i >= e) return;
    int s = src[i], d = dst[i];
    if ((unsigned)s >= (unsigned)n || (unsigned)d >= (unsigned)n) return;
    float w = g_dinv[s] * g_dinv[d];
    int pos = atomicAdd(&g_cnt[d], 1);
    g_edges[pos] = make_int2(s, __float_as_int(w));
}

// ---------------- W prep: fp32 [K][N] -> bf16 hi/lo transposed [N][K] -------
template <int K, int N>
__global__ void k_wprep(const float* __restrict__ W) {
    int i = blockIdx.x * blockDim.x + threadIdx.x;
    if (i >= K * N) return;
    int k = i / N, n = i % N;
    float v = W[i];
    __nv_bfloat16 h = __float2bfloat16(v);
    __nv_bfloat16 l = __float2bfloat16(v - __bfloat162float(h));
    g_wth[n * K + k] = h;
    g_wtl[n * K + k] = l;
}

// ---------------- bf16 mma ----------------
#define MMA_BF16(d, a, b0, b1)                                              \
    asm volatile(                                                           \
        "mma.sync.aligned.m16n8k16.row.col.f32.bf16.bf16.f32 "              \
        "{%0,%1,%2,%3}, {%4,%5,%6,%7}, {%8,%9}, {%0,%1,%2,%3};"             \
        : "+f"((d)[0]), "+f"((d)[1]), "+f"((d)[2]), "+f"((d)[3])            \
        : "r"((a)[0]), "r"((a)[1]), "r"((a)[2]), "r"((a)[3]),               \
          "r"(b0), "r"(b1))

// ---------------- tensor-core GEMM (3x bf16 split), raw output only --------
template <int KDIM, int NOUT, bool BNRELU>
__global__ void __launch_bounds__(256, 2)
k_gemm_bf16(const float* X, float* __restrict__ OUT, int nrows) {
    constexpr int BM = 128, BK = 16, KS = 24;
    constexpr int hN = NOUT / 2;
    constexpr int NT = hN / 8;
    constexpr int MT = 2;
    constexpr int KT = KDIM / BK;
    constexpr int WL = (NOUT == 128) ? 8 : 4;

    __shared__ __nv_bfloat16 Xh[2][BM][KS], Xl[2][BM][KS];
    __shared__ __nv_bfloat16 Wh[2][NOUT][KS], Wl[2][NOUT][KS];

    const int tid = threadIdx.x;
    const int lane = tid & 31;
    const int wid = tid >> 5;
    const int wm = wid & 3, wn = wid >> 2;
    const int row0 = blockIdx.x * BM;

    const int xr = tid >> 1;
    const int xkp = (tid & 1) * 8;
    const int wr = (NOUT == 128) ? (tid >> 1) : (tid >> 2);
    const int wkp = (NOUT == 128) ? (tid & 1) * 8 : (tid & 3) * 4;
    const int kc2 = (lane & 3) * 2;
    const int rfo = lane >> 2;

    float acc[MT][NT][4] = {};
    float xv[8];
    __nv_bfloat16 wvh[WL], wvl[WL];

    auto fetch = [&](int kb) {
        int row = row0 + xr;
#pragma unroll
        for (int i = 0; i < 2; i++) {
            float4 v = make_float4(0.f, 0.f, 0.f, 0.f);
            if (row < nrows)
                v = *reinterpret_cast<const float4*>(
                    &X[(size_t)row * KDIM + kb + xkp + i * 4]);
            xv[i * 4 + 0] = v.x; xv[i * 4 + 1] = v.y;
            xv[i * 4 + 2] = v.z; xv[i * 4 + 3] = v.w;
        }
        const __nv_bfloat16* ph = &g_wth[(size_t)wr * KDIM + kb + wkp];
        const __nv_bfloat16* pl = &g_wtl[(size_t)wr * KDIM + kb + wkp];
        if (WL == 8) {
            *reinterpret_cast<uint4*>(wvh) = *reinterpret_cast<const uint4*>(ph);
            *reinterpret_cast<uint4*>(wvl) = *reinterpret_cast<const uint4*>(pl);
        } else {
            *reinterpret_cast<uint2*>(wvh) = *reinterpret_cast<const uint2*>(ph);
            *reinterpret_cast<uint2*>(wvl) = *reinterpret_cast<const uint2*>(pl);
        }
    };

    auto stage = [&](int kb, int s) {
        __nv_bfloat16 hx[8], lx[8];
#pragma unroll
        for (int j = 0; j < 8; j++) {
            float v = xv[j];
            if (BNRELU)
                v = fmaxf(fmaf(v, g_bnsum[kb + xkp + j], g_bnsq[kb + xkp + j]), 0.f);
            __nv_bfloat16 h = __float2bfloat16(v);
            hx[j] = h;
            lx[j] = __float2bfloat16(v - __bfloat162float(h));
        }
        *reinterpret_cast<uint4*>(&Xh[s][xr][xkp]) = *reinterpret_cast<uint4*>(hx);
        *reinterpret_cast<uint4*>(&Xl[s][xr][xkp]) = *reinterpret_cast<uint4*>(lx);
        if (WL == 8) {
            *reinterpret_cast<uint4*>(&Wh[s][wr][wkp]) = *reinterpret_cast<uint4*>(wvh);
            *reinterpret_cast<uint4*>(&Wl[s][wr][wkp]) = *reinterpret_cast<uint4*>(wvl);
        } else {
            *reinterpret_cast<uint2*>(&Wh[s][wr][wkp]) = *reinterpret_cast<uint2*>(wvh);
            *reinterpret_cast<uint2*>(&Wl[s][wr][wkp]) = *reinterpret_cast<uint2*>(wvl);
        }
    };

    fetch(0);
    stage(0, 0);
    __syncthreads();

    for (int kt = 0; kt < KT; kt++) {
        const int s = kt & 1;
        const bool more = (kt + 1 < KT);
        if (more) fetch((kt + 1) * BK);

        unsigned ah[MT][4], al[MT][4];
#pragma unroll
        for (int mt = 0; mt < MT; mt++) {
            int ar = wm * 32 + mt * 16 + rfo;
            ah[mt][0] = *reinterpret_cast<const unsigned*>(&Xh[s][ar][kc2]);
            ah[mt][1] = *reinterpret_cast<const unsigned*>(&Xh[s][ar + 8][kc2]);
            ah[mt][2] = *reinterpret_cast<const unsigned*>(&Xh[s][ar][kc2 + 8]);
            ah[mt][3] = *reinterpret_cast<const unsigned*>(&Xh[s][ar + 8][kc2 + 8]);
            al[mt][0] = *reinterpret_cast<const unsigned*>(&Xl[s][ar][kc2]);
            al[mt][1] = *reinterpret_cast<const unsigned*>(&Xl[s][ar + 8][kc2]);
            al[mt][2] = *reinterpret_cast<const unsigned*>(&Xl[s][ar][kc2 + 8]);
            al[mt][3] = *reinterpret_cast<const unsigned*>(&Xl[s][ar + 8][kc2 + 8]);
        }
#pragma unroll
        for (int nt = 0; nt < NT; nt++) {
            int bn = wn * hN + nt * 8 + rfo;
            unsigned bh0 = *reinterpret_cast<const unsigned*>(&Wh[s][bn][kc2]);
            unsigned bh1 = *reinterpret_cast<const unsigned*>(&Wh[s][bn][kc2 + 8]);
            unsigned bl0 = *reinterpret_cast<const unsigned*>(&Wl[s][bn][kc2]);
            unsigned bl1 = *reinterpret_cast<const unsigned*>(&Wl[s][bn][kc2 + 8]);
#pragma unroll
            for (int mt = 0; mt < MT; mt++) MMA_BF16(acc[mt][nt], ah[mt], bh0, bh1);
#pragma unroll
            for (int mt = 0; mt < MT; mt++) MMA_BF16(acc[mt][nt], ah[mt], bl0, bl1);
#pragma unroll
            for (int mt = 0; mt < MT; mt++) MMA_BF16(acc[mt][nt], al[mt], bh0, bh1);
        }

        if (more) stage((kt + 1) * BK, s ^ 1);
        __syncthreads();
    }

#pragma unroll
    for (int mt = 0; mt < MT; mt++) {
        int r0 = row0 + wm * 32 + mt * 16 + rfo;
        int r1 = r0 + 8;
#pragma unroll
        for (int nt = 0; nt < NT; nt++) {
            int col = wn * hN + nt * 8 + (lane & 3) * 2;
            if (r0 < nrows)
                *reinterpret_cast<float2*>(&OUT[(size_t)r0 * NOUT + col]) =
                    make_float2(acc[mt][nt][0], acc[mt][nt][1]);
            if (r1 < nrows)
                *reinterpret_cast<float2*>(&OUT[(size_t)r1 * NOUT + col]) =
                    make_float2(acc[mt][nt][2], acc[mt][nt][3]);
        }
    }
}

// ---------------- CSR aggregation (gather): out[d] = h[d]*dinv^2 + sum ------
template <int NOUT, bool BNSTAT>
__global__ void __launch_bounds__(256)
k_aggr(const float* __restrict__ h, float* __restrict__ out, int n) {
    constexpr int LPN = NOUT / 4;
    constexpr int NPW = 32 / LPN;
    constexpr int NPB = 8 * NPW;
    __shared__ float ss[BNSTAT ? DHID : 1], sq[BNSTAT ? DHID : 1];

    int tid = threadIdx.x;
    int warp = tid >> 5, lane = tid & 31;
    if (BNSTAT) {
        if (tid < NOUT) { ss[tid] = 0.0f; sq[tid] = 0.0f; }
        __syncthreads();
    }

    int node = blockIdx.x * NPB + warp * NPW + lane / LPN;
    int c = (lane % LPN) * 4;
    float4 acc = make_float4(0.f, 0.f, 0.f, 0.f);
    bool active = (node < n);

    if (active) {
        float di = g_dinv[node];
        di *= di;
        float4 v = *reinterpret_cast<const float4*>(&h[(size_t)node * NOUT + c]);
        acc = make_float4(v.x * di, v.y * di, v.z * di, v.w * di);

        int i = g_off[node], e1 = g_off[node + 1];
        for (; i + 2 <= e1; i += 2) {
            int2 ea = g_edges[i], eb = g_edges[i + 1];
            float wa = __int_as_float(ea.y), wb = __int_as_float(eb.y);
            float4 va = *reinterpret_cast<const float4*>(&h[(size_t)ea.x * NOUT + c]);
            float4 vb = *reinterpret_cast<const float4*>(&h[(size_t)eb.x * NOUT + c]);
            acc.x = fmaf(va.x, wa, acc.x); acc.y = fmaf(va.y, wa, acc.y);
            acc.z = fmaf(va.z, wa, acc.z); acc.w = fmaf(va.w, wa, acc.w);
            acc.x = fmaf(vb.x, wb, acc.x); acc.y = fmaf(vb.y, wb, acc.y);
            acc.z = fmaf(vb.z, wb, acc.z); acc.w = fmaf(vb.w, wb, acc.w);
        }
        if (i < e1) {
            int2 e = g_edges[i];
            float w = __int_as_float(e.y);
            float4 v2 = *reinterpret_cast<const float4*>(&h[(size_t)e.x * NOUT + c]);
            acc.x = fmaf(v2.x, w, acc.x); acc.y = fmaf(v2.y, w, acc.y);
            acc.z = fmaf(v2.z, w, acc.z); acc.w = fmaf(v2.w, w, acc.w);
        }
        *reinterpret_cast<float4*>(&out[(size_t)node * NOUT + c]) = acc;
    }

    if (BNSTAT) {
        if (active) {
            atomicAdd(&ss[c + 0], acc.x); atomicAdd(&sq[c + 0], acc.x * acc.x);
            atomicAdd(&ss[c + 1], acc.y); atomicAdd(&sq[c + 1], acc.y * acc.y);
            atomicAdd(&ss[c + 2], acc.z); atomicAdd(&sq[c + 2], acc.z * acc.z);
            atomicAdd(&ss[c + 3], acc.w); atomicAdd(&sq[c + 3], acc.w * acc.w);
        }
        __syncthreads();
        if (tid < NOUT) {
            atomicAdd(&g_stat_s[tid], ss[tid]);
            atomicAdd(&g_stat_q[tid], sq[tid]);
        }
    }
}

// ---------------- BN finalize: stats -> (scale, shift); re-zero stats -------
__global__ void k_bnfinal(const float* __restrict__ gam, const float* __restrict__ bet, float n) {
    int c = threadIdx.x;  // 128
    float s = g_stat_s[c], q = g_stat_q[c];
    float mu = s / n;
    float var = q / n - mu * mu;
    float sc = rsqrtf(var + BN_EPS) * gam[c];
    g_bnsum[c] = sc;
    g_bnsq[c] = bet[c] - mu * sc;
    g_stat_s[c] = 0.0f;
    g_stat_q[c] = 0.0f;
}

// ---------------- pool: batch sorted -> run-length accumulate ----------------
#define POOL_CHUNK 128
__global__ void k_pool(const float* __restrict__ h, const int* __restrict__ batch, int n) {
    int col = threadIdx.x;  // 64
    int r0 = blockIdx.x * POOL_CHUNK;
    if (r0 >= n) return;
    int r1 = min(r0 + POOL_CHUNK, n);
    int cur = batch[r0] & (NGRAPH - 1);
    float acc = 0.0f, cacc = 0.0f;
    for (int r = r0; r < r1; r++) {
        int g = batch[r] & (NGRAPH - 1);
        if (g != cur) {
            atomicAdd(&g_pool[cur * DOUT + col], acc);
            if (col == 0) atomicAdd(&g_pcnt[cur], cacc);
            acc = 0.0f; cacc = 0.0f; cur = g;
        }
        acc += h[(size_t)r * DOUT + col];
        cacc += 1.0f;
    }
    atomicAdd(&g_pool[cur * DOUT + col], acc);
    if (col == 0) atomicAdd(&g_pcnt[cur], cacc);
}

__global__ void k_final(float* __restrict__ out, const float* __restrict__ b3) {
    int t = threadIdx.x;  // 1024
    int g = t / DOUT;
    int c = t % DOUT;
    float cnt = g_pcnt[g];
    out[t] = (cnt > 0.0f) ? (g_pool[t] / cnt + b3[c]) : 0.0f;
}

// ============================================================================
extern "C" void kernel_launch(void* const* d_in, const int* in_sizes, int n_in,
                              void* d_out, int out_size) {
    const float* x     = (const float*)d_in[0];
    const int*   ei    = (const int*)d_in[1];   // int64 coerced to int32
    const int*   batch = (const int*)d_in[2];
    const float* W1    = (const float*)d_in[3];
    const float* W2    = (const float*)d_in[5];
    const float* W3    = (const float*)d_in[7];
    const float* b3    = (const float*)d_in[8];
    const float* g1    = (const float*)d_in[9];
    const float* be1   = (const float*)d_in[10];
    const float* g2    = (const float*)d_in[11];
    const float* be2   = (const float*)d_in[12];
    float* out = (float*)d_out;

    const int n = in_sizes[2];       // 50000
    const int E = in_sizes[1] / 2;   // 800000
    const int* src = ei;
    const int* dst = ei + E;

    float* bufA; float* bufB;
    cudaGetSymbolAddress((void**)&bufA, g_bufA);
    cudaGetSymbolAddress((void**)&bufB, g_bufB);
    float* raw3 = bufA;
    float* agg3 = bufA + (size_t)NN * DOUT;

    const int TB = 256;
    int nb_n    = (n + TB - 1) / TB;
    int nb_e    = (E + TB - 1) / TB;
    int nb_scan = (n + SCAN_B - 1) / SCAN_B;     // 196 <= 256
    int nb_gemm = (n + 127) / 128;
    int nb_ag128 = (n + 7) / 8;
    int nb_ag64  = (n + 15) / 16;
    int nb_pool  = (n + POOL_CHUNK - 1) / POOL_CHUNK;

    // ---- graph preprocessing: degree, dinv, CSR (parallel scan) ----
    k_init<<<nb_n, TB>>>(n);
    k_cnt<<<nb_e, TB>>>(dst, E, n);
    k_dinv<<<nb_n, TB>>>(n);
    k_scanA<<<nb_scan, SCAN_B>>>(n);
    k_scanB<<<1, SCAN_B>>>(nb_scan, n);
    k_scanC<<<nb_scan, SCAN_B>>>(n);
    k_fill<<<nb_e, TB>>>(src, dst, E, n);

    // ---- layer 1 ----
    k_wprep<256, 128><<<(256 * 128 + TB - 1) / TB, TB>>>(W1);
    k_gemm_bf16<256, 128, false><<<nb_gemm, 256>>>(x, bufA, n);
    k_aggr<128, true><<<nb_ag128, 256>>>(bufA, bufB, n);
    k_bnfinal<<<1, DHID>>>(g1, be1, (float)n);

    // ---- layer 2 (BN1+ReLU fused into gemm X load) ----
    k_wprep<128, 128><<<(128 * 128 + TB - 1) / TB, TB>>>(W2);
    k_gemm_bf16<128, 128, true><<<nb_gemm, 256>>>(bufB, bufA, n);
    k_aggr<128, true><<<nb_ag128, 256>>>(bufA, bufB, n);
    k_bnfinal<<<1, DHID>>>(g2, be2, (float)n);

    // ---- layer 3 (BN2+ReLU fused) ----
    k_wprep<128, 64><<<(128 * 64 + TB - 1) / TB, TB>>>(W3);
    k_gemm_bf16<128, 64, true><<<nb_gemm, 256>>>(bufB, raw3, n);
    k_aggr<64, false><<<nb_ag64, 256>>>(raw3, agg3, n);

    // ---- mean pool + bias ----
    k_pool<<<nb_pool, DOUT>>>(agg3, batch, n);
    k_final<<<1, NGRAPH * DOUT>>>(out, b3);
}

// round 10
// speedup vs baseline: 2.0526x; 1.0088x over previous
#include <cuda_runtime.h>
#include <cuda_bf16.h>
#include <math.h>
#include <stdint.h>

// ---------------- problem constants ----------------
#define NN 50000
#define EMAX 800000
#define DHID 128
#define DOUT 64
#define NGRAPH 16
#define BN_EPS 1e-5f
#define MAXK 256
#define SCAN_B 256

// ---------------- device scratch ----------------
__device__ __align__(16) float g_dinv[NN];
__device__ __align__(16) int   g_cnt[NN];        // counts, then fill cursor
__device__ __align__(16) int   g_off[NN + 1];    // CSR offsets
__device__ __align__(16) int   g_bsum[SCAN_B];   // scan block partials
__device__ __align__(16) int2  g_edges[EMAX];    // (src, bitcast w)
__device__ __align__(16) float g_bufA[NN * DHID];
__device__ __align__(16) float g_bufB[NN * DHID];
__device__ __align__(16) __nv_bfloat16 g_wth[MAXK * DHID];   // W^T hi [N][K]
__device__ __align__(16) __nv_bfloat16 g_wtl[MAXK * DHID];   // W^T lo
__device__ __align__(16) float g_stat_s[DHID];   // BN accumulation
__device__ __align__(16) float g_stat_q[DHID];
__device__ __align__(16) float g_bnsum[DHID];    // BN scale (by k)
__device__ __align__(16) float g_bnsq[DHID];     // BN shift (by k)
__device__ __align__(16) float g_pool[NGRAPH * DOUT];
__device__ __align__(16) float g_pcnt[NGRAPH];

// ---------------- init ----------------
__global__ void k_init(int n) {
    int i = blockIdx.x * blockDim.x + threadIdx.x;
    if (i < n) g_cnt[i] = 0;
    if (i < DHID) { g_stat_s[i] = 0.0f; g_stat_q[i] = 0.0f; }
    if (i < NGRAPH * DOUT) g_pool[i] = 0.0f;
    if (i < NGRAPH) g_pcnt[i] = 0.0f;
}

__global__ void k_cnt(const int* __restrict__ dst, int e, int n) {
    int i = blockIdx.x * blockDim.x + threadIdx.x;
    if (i < e) {
        int d = dst[i];
        if ((unsigned)d < (unsigned)n) atomicAdd(&g_cnt[d], 1);
    }
}

// deg = cnt + 1 (self loop)
__global__ void k_dinv(int n) {
    int i = blockIdx.x * blockDim.x + threadIdx.x;
    if (i < n) g_dinv[i] = rsqrtf((float)g_cnt[i] + 1.0f);
}

// ---------------- 3-phase parallel exclusive scan over g_cnt ----------------
__global__ void k_scanA(int n) {
    __shared__ int sh[SCAN_B];
    int t = threadIdx.x;
    int i = blockIdx.x * SCAN_B + t;
    sh[t] = (i < n) ? g_cnt[i] : 0;
    __syncthreads();
#pragma unroll
    for (int d = SCAN_B / 2; d > 0; d >>= 1) {
        if (t < d) sh[t] += sh[t + d];
        __syncthreads();
    }
    if (t == 0) g_bsum[blockIdx.x] = sh[0];
}

__global__ void k_scanB(int nblocks, int n) {
    __shared__ int sh[SCAN_B];
    int t = threadIdx.x;
    int v = (t < nblocks) ? g_bsum[t] : 0;
    sh[t] = v;
    __syncthreads();
#pragma unroll
    for (int d = 1; d < SCAN_B; d <<= 1) {
        int x = (t >= d) ? sh[t - d] : 0;
        __syncthreads();
        sh[t] += x;
        __syncthreads();
    }
    if (t < nblocks) g_bsum[t] = sh[t] - v;
    if (t == SCAN_B - 1) g_off[n] = sh[t];
}

__global__ void k_scanC(int n) {
    __shared__ int sh[SCAN_B];
    int t = threadIdx.x;
    int i = blockIdx.x * SCAN_B + t;
    int v = (i < n) ? g_cnt[i] : 0;
    sh[t] = v;
    __syncthreads();
#pragma unroll
    for (int d = 1; d < SCAN_B; d <<= 1) {
        int x = (t >= d) ? sh[t - d] : 0;
        __syncthreads();
        sh[t] += x;
        __syncthreads();
    }
    if (i < n) {
        int off = g_bsum[blockIdx.x] + sh[t] - v;
        g_off[i] = off;
        g_cnt[i] = off;
    }
}

__global__ void k_fill(const int* __restrict__ src, const int* __restrict__ dst,
                       int e, int n) {
    int i = blockIdx.x * blockDim.x + threadIdx.x;
    if (i >= e) return;
    int s = src[i], d = dst[i];
    if ((unsigned)s >= (unsigned)n || (unsigned)d >= (unsigned)n) return;
    float w = g_dinv[s] * g_dinv[d];
    int pos = atomicAdd(&g_cnt[d], 1);
    g_edges[pos] = make_int2(s, __float_as_int(w));
}

// ---------------- W prep: fp32 [K][N] -> bf16 hi/lo transposed [N][K] -------
template <int K, int N>
__global__ void k_wprep(const float* __restrict__ W) {
    int i = blockIdx.x * blockDim.x + threadIdx.x;
    if (i >= K * N) return;
    int k = i / N, n = i % N;
    float v = W[i];
    __nv_bfloat16 h = __float2bfloat16(v);
    __nv_bfloat16 l = __float2bfloat16(v - __bfloat162float(h));
    g_wth[n * K + k] = h;
    g_wtl[n * K + k] = l;
}

// ---------------- bf16 mma ----------------
#define MMA_BF16(d, a, b0, b1)                                              \
    asm volatile(                                                           \
        "mma.sync.aligned.m16n8k16.row.col.f32.bf16.bf16.f32 "              \
        "{%0,%1,%2,%3}, {%4,%5,%6,%7}, {%8,%9}, {%0,%1,%2,%3};"             \
        : "+f"((d)[0]), "+f"((d)[1]), "+f"((d)[2]), "+f"((d)[3])            \
        : "r"((a)[0]), "r"((a)[1]), "r"((a)[2]), "r"((a)[3]),               \
          "r"(b0), "r"(b1))

// ---------------- tensor-core GEMM (3x bf16 split), raw output only --------
template <int KDIM, int NOUT, bool BNRELU>
__global__ void __launch_bounds__(256, 2)
k_gemm_bf16(const float* X, float* __restrict__ OUT, int nrows) {
    constexpr int BM = 128, BK = 16, KS = 24;
    constexpr int hN = NOUT / 2;
    constexpr int NT = hN / 8;
    constexpr int MT = 2;
    constexpr int KT = KDIM / BK;
    constexpr int WL = (NOUT == 128) ? 8 : 4;

    __shared__ __nv_bfloat16 Xh[2][BM][KS], Xl[2][BM][KS];
    __shared__ __nv_bfloat16 Wh[2][NOUT][KS], Wl[2][NOUT][KS];

    const int tid = threadIdx.x;
    const int lane = tid & 31;
    const int wid = tid >> 5;
    const int wm = wid & 3, wn = wid >> 2;
    const int row0 = blockIdx.x * BM;

    const int xr = tid >> 1;
    const int xkp = (tid & 1) * 8;
    const int wr = (NOUT == 128) ? (tid >> 1) : (tid >> 2);
    const int wkp = (NOUT == 128) ? (tid & 1) * 8 : (tid & 3) * 4;
    const int kc2 = (lane & 3) * 2;
    const int rfo = lane >> 2;

    float acc[MT][NT][4] = {};
    float xv[8];
    __nv_bfloat16 wvh[WL], wvl[WL];

    auto fetch = [&](int kb) {
        int row = row0 + xr;
#pragma unroll
        for (int i = 0; i < 2; i++) {
            float4 v = make_float4(0.f, 0.f, 0.f, 0.f);
            if (row < nrows)
                v = *reinterpret_cast<const float4*>(
                    &X[(size_t)row * KDIM + kb + xkp + i * 4]);
            xv[i * 4 + 0] = v.x; xv[i * 4 + 1] = v.y;
            xv[i * 4 + 2] = v.z; xv[i * 4 + 3] = v.w;
        }
        const __nv_bfloat16* ph = &g_wth[(size_t)wr * KDIM + kb + wkp];
        const __nv_bfloat16* pl = &g_wtl[(size_t)wr * KDIM + kb + wkp];
        if (WL == 8) {
            *reinterpret_cast<uint4*>(wvh) = *reinterpret_cast<const uint4*>(ph);
            *reinterpret_cast<uint4*>(wvl) = *reinterpret_cast<const uint4*>(pl);
        } else {
            *reinterpret_cast<uint2*>(wvh) = *reinterpret_cast<const uint2*>(ph);
            *reinterpret_cast<uint2*>(wvl) = *reinterpret_cast<const uint2*>(pl);
        }
    };

    auto stage = [&](int kb, int s) {
        __nv_bfloat16 hx[8], lx[8];
#pragma unroll
        for (int j = 0; j < 8; j++) {
            float v = xv[j];
            if (BNRELU)
                v = fmaxf(fmaf(v, g_bnsum[kb + xkp + j], g_bnsq[kb + xkp + j]), 0.f);
            __nv_bfloat16 h = __float2bfloat16(v);
            hx[j] = h;
            lx[j] = __float2bfloat16(v - __bfloat162float(h));
        }
        *reinterpret_cast<uint4*>(&Xh[s][xr][xkp]) = *reinterpret_cast<uint4*>(hx);
        *reinterpret_cast<uint4*>(&Xl[s][xr][xkp]) = *reinterpret_cast<uint4*>(lx);
        if (WL == 8) {
            *reinterpret_cast<uint4*>(&Wh[s][wr][wkp]) = *reinterpret_cast<uint4*>(wvh);
            *reinterpret_cast<uint4*>(&Wl[s][wr][wkp]) = *reinterpret_cast<uint4*>(wvl);
        } else {
            *reinterpret_cast<uint2*>(&Wh[s][wr][wkp]) = *reinterpret_cast<uint2*>(wvh);
            *reinterpret_cast<uint2*>(&Wl[s][wr][wkp]) = *reinterpret_cast<uint2*>(wvl);
        }
    };

    fetch(0);
    stage(0, 0);
    __syncthreads();

    for (int kt = 0; kt < KT; kt++) {
        const int s = kt & 1;
        const bool more = (kt + 1 < KT);
        if (more) fetch((kt + 1) * BK);

        unsigned ah[MT][4], al[MT][4];
#pragma unroll
        for (int mt = 0; mt < MT; mt++) {
            int ar = wm * 32 + mt * 16 + rfo;
            ah[mt][0] = *reinterpret_cast<const unsigned*>(&Xh[s][ar][kc2]);
            ah[mt][1] = *reinterpret_cast<const unsigned*>(&Xh[s][ar + 8][kc2]);
            ah[mt][2] = *reinterpret_cast<const unsigned*>(&Xh[s][ar][kc2 + 8]);
            ah[mt][3] = *reinterpret_cast<const unsigned*>(&Xh[s][ar + 8][kc2 + 8]);
            al[mt][0] = *reinterpret_cast<const unsigned*>(&Xl[s][ar][kc2]);
            al[mt][1] = *reinterpret_cast<const unsigned*>(&Xl[s][ar + 8][kc2]);
            al[mt][2] = *reinterpret_cast<const unsigned*>(&Xl[s][ar][kc2 + 8]);
            al[mt][3] = *reinterpret_cast<const unsigned*>(&Xl[s][ar + 8][kc2 + 8]);
        }
#pragma unroll
        for (int nt = 0; nt < NT; nt++) {
            int bn = wn * hN + nt * 8 + rfo;
            unsigned bh0 = *reinterpret_cast<const unsigned*>(&Wh[s][bn][kc2]);
            unsigned bh1 = *reinterpret_cast<const unsigned*>(&Wh[s][bn][kc2 + 8]);
            unsigned bl0 = *reinterpret_cast<const unsigned*>(&Wl[s][bn][kc2]);
            unsigned bl1 = *reinterpret_cast<const unsigned*>(&Wl[s][bn][kc2 + 8]);
#pragma unroll
            for (int mt = 0; mt < MT; mt++) MMA_BF16(acc[mt][nt], ah[mt], bh0, bh1);
#pragma unroll
            for (int mt = 0; mt < MT; mt++) MMA_BF16(acc[mt][nt], ah[mt], bl0, bl1);
#pragma unroll
            for (int mt = 0; mt < MT; mt++) MMA_BF16(acc[mt][nt], al[mt], bh0, bh1);
        }

        if (more) stage((kt + 1) * BK, s ^ 1);
        __syncthreads();
    }

#pragma unroll
    for (int mt = 0; mt < MT; mt++) {
        int r0 = row0 + wm * 32 + mt * 16 + rfo;
        int r1 = r0 + 8;
#pragma unroll
        for (int nt = 0; nt < NT; nt++) {
            int col = wn * hN + nt * 8 + (lane & 3) * 2;
            if (r0 < nrows)
                *reinterpret_cast<float2*>(&OUT[(size_t)r0 * NOUT + col]) =
                    make_float2(acc[mt][nt][0], acc[mt][nt][1]);
            if (r1 < nrows)
                *reinterpret_cast<float2*>(&OUT[(size_t)r1 * NOUT + col]) =
                    make_float2(acc[mt][nt][2], acc[mt][nt][3]);
        }
    }
}

// ---------------- CSR aggregation (gather): out[d] = h[d]*dinv^2 + sum ------
// 4-edge software pipeline: batch 4 edge records, then 4 independent row
// gathers in flight per lane (MLP_eff ~4) before the FMA chain.
template <int NOUT, bool BNSTAT>
__global__ void __launch_bounds__(256, 6)
k_aggr(const float* __restrict__ h, float* __restrict__ out, int n) {
    constexpr int LPN = NOUT / 4;
    constexpr int NPW = 32 / LPN;
    constexpr int NPB = 8 * NPW;
    __shared__ float ss[BNSTAT ? DHID : 1], sq[BNSTAT ? DHID : 1];

    int tid = threadIdx.x;
    int warp = tid >> 5, lane = tid & 31;
    if (BNSTAT) {
        if (tid < NOUT) { ss[tid] = 0.0f; sq[tid] = 0.0f; }
        __syncthreads();
    }

    int node = blockIdx.x * NPB + warp * NPW + lane / LPN;
    int c = (lane % LPN) * 4;
    float4 acc = make_float4(0.f, 0.f, 0.f, 0.f);
    bool active = (node < n);

    if (active) {
        float di = g_dinv[node];
        di *= di;
        float4 v = *reinterpret_cast<const float4*>(&h[(size_t)node * NOUT + c]);
        acc = make_float4(v.x * di, v.y * di, v.z * di, v.w * di);

        int i = g_off[node], e1 = g_off[node + 1];

        // 4-edge pipelined main loop
        for (; i + 4 <= e1; i += 4) {
            int2 e0 = g_edges[i + 0];
            int2 e1r = g_edges[i + 1];
            int2 e2 = g_edges[i + 2];
            int2 e3 = g_edges[i + 3];
            const float4 v0 = *reinterpret_cast<const float4*>(&h[(size_t)e0.x * NOUT + c]);
            const float4 v1 = *reinterpret_cast<const float4*>(&h[(size_t)e1r.x * NOUT + c]);
            const float4 v2 = *reinterpret_cast<const float4*>(&h[(size_t)e2.x * NOUT + c]);
            const float4 v3 = *reinterpret_cast<const float4*>(&h[(size_t)e3.x * NOUT + c]);
            float w0 = __int_as_float(e0.y), w1 = __int_as_float(e1r.y);
            float w2 = __int_as_float(e2.y), w3 = __int_as_float(e3.y);
            acc.x = fmaf(v0.x, w0, acc.x); acc.y = fmaf(v0.y, w0, acc.y);
            acc.z = fmaf(v0.z, w0, acc.z); acc.w = fmaf(v0.w, w0, acc.w);
            acc.x = fmaf(v1.x, w1, acc.x); acc.y = fmaf(v1.y, w1, acc.y);
            acc.z = fmaf(v1.z, w1, acc.z); acc.w = fmaf(v1.w, w1, acc.w);
            acc.x = fmaf(v2.x, w2, acc.x); acc.y = fmaf(v2.y, w2, acc.y);
            acc.z = fmaf(v2.z, w2, acc.z); acc.w = fmaf(v2.w, w2, acc.w);
            acc.x = fmaf(v3.x, w3, acc.x); acc.y = fmaf(v3.y, w3, acc.y);
            acc.z = fmaf(v3.z, w3, acc.z); acc.w = fmaf(v3.w, w3, acc.w);
        }
        // 2-edge tail
        if (i + 2 <= e1) {
            int2 e0 = g_edges[i + 0];
            int2 e1r = g_edges[i + 1];
            const float4 v0 = *reinterpret_cast<const float4*>(&h[(size_t)e0.x * NOUT + c]);
            const float4 v1 = *reinterpret_cast<const float4*>(&h[(size_t)e1r.x * NOUT + c]);
            float w0 = __int_as_float(e0.y), w1 = __int_as_float(e1r.y);
            acc.x = fmaf(v0.x, w0, acc.x); acc.y = fmaf(v0.y, w0, acc.y);
            acc.z = fmaf(v0.z, w0, acc.z); acc.w = fmaf(v0.w, w0, acc.w);
            acc.x = fmaf(v1.x, w1, acc.x); acc.y = fmaf(v1.y, w1, acc.y);
            acc.z = fmaf(v1.z, w1, acc.z); acc.w = fmaf(v1.w, w1, acc.w);
            i += 2;
        }
        if (i < e1) {
            int2 e = g_edges[i];
            float w = __int_as_float(e.y);
            const float4 v2 = *reinterpret_cast<const float4*>(&h[(size_t)e.x * NOUT + c]);
            acc.x = fmaf(v2.x, w, acc.x); acc.y = fmaf(v2.y, w, acc.y);
            acc.z = fmaf(v2.z, w, acc.z); acc.w = fmaf(v2.w, w, acc.w);
        }
        *reinterpret_cast<float4*>(&out[(size_t)node * NOUT + c]) = acc;
    }

    if (BNSTAT) {
        if (active) {
            atomicAdd(&ss[c + 0], acc.x); atomicAdd(&sq[c + 0], acc.x * acc.x);
            atomicAdd(&ss[c + 1], acc.y); atomicAdd(&sq[c + 1], acc.y * acc.y);
            atomicAdd(&ss[c + 2], acc.z); atomicAdd(&sq[c + 2], acc.z * acc.z);
            atomicAdd(&ss[c + 3], acc.w); atomicAdd(&sq[c + 3], acc.w * acc.w);
        }
        __syncthreads();
        if (tid < NOUT) {
            atomicAdd(&g_stat_s[tid], ss[tid]);
            atomicAdd(&g_stat_q[tid], sq[tid]);
        }
    }
}

// ---------------- BN finalize: stats -> (scale, shift); re-zero stats -------
__global__ void k_bnfinal(const float* __restrict__ gam, const float* __restrict__ bet, float n) {
    int c = threadIdx.x;  // 128
    float s = g_stat_s[c], q = g_stat_q[c];
    float mu = s / n;
    float var = q / n - mu * mu;
    float sc = rsqrtf(var + BN_EPS) * gam[c];
    g_bnsum[c] = sc;
    g_bnsq[c] = bet[c] - mu * sc;
    g_stat_s[c] = 0.0f;
    g_stat_q[c] = 0.0f;
}

// ---------------- pool: batch sorted -> run-length accumulate ----------------
#define POOL_CHUNK 128
__global__ void k_pool(const float* __restrict__ h, const int* __restrict__ batch, int n) {
    int col = threadIdx.x;  // 64
    int r0 = blockIdx.x * POOL_CHUNK;
    if (r0 >= n) return;
    int r1 = min(r0 + POOL_CHUNK, n);
    int cur = batch[r0] & (NGRAPH - 1);
    float acc = 0.0f, cacc = 0.0f;
    for (int r = r0; r < r1; r++) {
        int g = batch[r] & (NGRAPH - 1);
        if (g != cur) {
            atomicAdd(&g_pool[cur * DOUT + col], acc);
            if (col == 0) atomicAdd(&g_pcnt[cur], cacc);
            acc = 0.0f; cacc = 0.0f; cur = g;
        }
        acc += h[(size_t)r * DOUT + col];
        cacc += 1.0f;
    }
    atomicAdd(&g_pool[cur * DOUT + col], acc);
    if (col == 0) atomicAdd(&g_pcnt[cur], cacc);
}

__global__ void k_final(float* __restrict__ out, const float* __restrict__ b3) {
    int t = threadIdx.x;  // 1024
    int g = t / DOUT;
    int c = t % DOUT;
    float cnt = g_pcnt[g];
    out[t] = (cnt > 0.0f) ? (g_pool[t] / cnt + b3[c]) : 0.0f;
}

// ============================================================================
extern "C" void kernel_launch(void* const* d_in, const int* in_sizes, int n_in,
                              void* d_out, int out_size) {
    const float* x     = (const float*)d_in[0];
    const int*   ei    = (const int*)d_in[1];   // int64 coerced to int32
    const int*   batch = (const int*)d_in[2];
    const float* W1    = (const float*)d_in[3];
    const float* W2    = (const float*)d_in[5];
    const float* W3    = (const float*)d_in[7];
    const float* b3    = (const float*)d_in[8];
    const float* g1    = (const float*)d_in[9];
    const float* be1   = (const float*)d_in[10];
    const float* g2    = (const float*)d_in[11];
    const float* be2   = (const float*)d_in[12];
    float* out = (float*)d_out;

    const int n = in_sizes[2];       // 50000
    const int E = in_sizes[1] / 2;   // 800000
    const int* src = ei;
    const int* dst = ei + E;

    float* bufA; float* bufB;
    cudaGetSymbolAddress((void**)&bufA, g_bufA);
    cudaGetSymbolAddress((void**)&bufB, g_bufB);
    float* raw3 = bufA;
    float* agg3 = bufA + (size_t)NN * DOUT;

    const int TB = 256;
    int nb_n    = (n + TB - 1) / TB;
    int nb_e    = (E + TB - 1) / TB;
    int nb_scan = (n + SCAN_B - 1) / SCAN_B;
    int nb_gemm = (n + 127) / 128;
    int nb_ag128 = (n + 7) / 8;
    int nb_ag64  = (n + 15) / 16;
    int nb_pool  = (n + POOL_CHUNK - 1) / POOL_CHUNK;

    // ---- graph preprocessing: degree, dinv, CSR ----
    k_init<<<nb_n, TB>>>(n);
    k_cnt<<<nb_e, TB>>>(dst, E, n);
    k_dinv<<<nb_n, TB>>>(n);
    k_scanA<<<nb_scan, SCAN_B>>>(n);
    k_scanB<<<1, SCAN_B>>>(nb_scan, n);
    k_scanC<<<nb_scan, SCAN_B>>>(n);
    k_fill<<<nb_e, TB>>>(src, dst, E, n);

    // ---- layer 1 ----
    k_wprep<256, 128><<<(256 * 128 + TB - 1) / TB, TB>>>(W1);
    k_gemm_bf16<256, 128, false><<<nb_gemm, 256>>>(x, bufA, n);
    k_aggr<128, true><<<nb_ag128, 256>>>(bufA, bufB, n);
    k_bnfinal<<<1, DHID>>>(g1, be1, (float)n);

    // ---- layer 2 (BN1+ReLU fused into gemm X load) ----
    k_wprep<128, 128><<<(128 * 128 + TB - 1) / TB, TB>>>(W2);
    k_gemm_bf16<128, 128, true><<<nb_gemm, 256>>>(bufB, bufA, n);
    k_aggr<128, true><<<nb_ag128, 256>>>(bufA, bufB, n);
    k_bnfinal<<<1, DHID>>>(g2, be2, (float)n);

    // ---- layer 3 (BN2+ReLU fused) ----
    k_wprep<128, 64><<<(128 * 64 + TB - 1) / TB, TB>>>(W3);
    k_gemm_bf16<128, 64, true><<<nb_gemm, 256>>>(bufB, raw3, n);
    k_aggr<64, false><<<nb_ag64, 256>>>(raw3, agg3, n);

    // ---- mean pool + bias ----
    k_pool<<<nb_pool, DOUT>>>(agg3, batch, n);
    k_final<<<1, NGRAPH * DOUT>>>(out, b3);
}